// round 7
// baseline (speedup 1.0000x reference)
#include <cuda_runtime.h>

#define LSEQ 2048
#define BB 2
#define HIDD 1024
#define HEADS 16
#define DH 64
#define NTOK (LSEQ*BB)

// ---------------- scratch (device globals; no allocation allowed) ----------------
__device__ float g_Q[(size_t)BB*HEADS*LSEQ*DH];
__device__ float g_K[(size_t)BB*HEADS*LSEQ*DH];
__device__ float g_V[(size_t)BB*HEADS*LSEQ*DH];
__device__ float g_ctx[(size_t)NTOK*HIDD];
__device__ float g_mb[BB*LSEQ];

// ---------------- mask normalization (dtype-robust) ----------------
// mask may arrive as bool (1B), int32 (4B) or float32 (4B). Values are only 0/1.
//  - any byte > 1            -> float32 storage (e.g. 1.0f has bytes 0x80,0x3f)
//  - any nonzero byte at i%4!=0 (values 0/1 only) -> 1-byte bool storage
//  - else                    -> int32 little-endian storage
__global__ void prep_mask(const unsigned char* __restrict__ mraw) {
    __shared__ int s_u8, s_f32;
    int t = threadIdx.x;
    if (t == 0) { s_u8 = 0; s_f32 = 0; }
    __syncthreads();
    int u8 = 0, f32 = 0;
    for (int i = t; i < BB*LSEQ; i += blockDim.x) {
        unsigned char v = mraw[i];
        if (v > 1) f32 = 1;
        if ((i & 3) != 0 && v) u8 = 1;
    }
    if (u8)  atomicOr(&s_u8, 1);
    if (f32) atomicOr(&s_f32, 1);
    __syncthreads();
    int is_f32 = s_f32, is_u8 = s_u8;
    for (int i = t; i < BB*LSEQ; i += blockDim.x) {
        bool m;
        if (is_f32)      m = (((const float*)mraw)[i] != 0.0f);
        else if (is_u8)  m = (mraw[i] != 0);
        else             m = (((const int*)mraw)[i] != 0);
        g_mb[i] = m ? -1e30f : 0.0f;
    }
}

// ---------------- GEMM: Y = X @ W^T + bias ----------------
// X: [NTOK, HIDD] row-major (row r = l*B + b), W: [out, in] row-major.
// omode 0/1/2 : scatter into g_Q/g_K/g_V with layout [b][h][l][d]
// omode 3     : plain [r][o] into Yext (used for final FC -> d_out)
// xsel 1      : X taken from g_ctx (device global) instead of param.
__global__ __launch_bounds__(256) void gemm_wt(
    const float* __restrict__ Xp, const float* __restrict__ W,
    const float* __restrict__ bias, float* __restrict__ Yext,
    int xsel, int omode)
{
    const float* X = xsel ? g_ctx : Xp;
    __shared__ float As[16][128];
    __shared__ float Bs[16][128];
    int tid = threadIdx.x;
    int m0 = blockIdx.y * 128, n0 = blockIdx.x * 128;
    int tx = tid & 15, ty = tid >> 4;

    float acc[8][8];
#pragma unroll
    for (int i = 0; i < 8; i++)
#pragma unroll
        for (int j = 0; j < 8; j++) acc[i][j] = 0.0f;

    for (int kt = 0; kt < HIDD; kt += 16) {
#pragma unroll
        for (int i = tid; i < 512; i += 256) {
            int row = i >> 2, c4 = (i & 3) << 2;
            float4 a = *(const float4*)(X + (size_t)(m0 + row) * HIDD + kt + c4);
            As[c4 + 0][row] = a.x; As[c4 + 1][row] = a.y;
            As[c4 + 2][row] = a.z; As[c4 + 3][row] = a.w;
            float4 b = *(const float4*)(W + (size_t)(n0 + row) * HIDD + kt + c4);
            Bs[c4 + 0][row] = b.x; Bs[c4 + 1][row] = b.y;
            Bs[c4 + 2][row] = b.z; Bs[c4 + 3][row] = b.w;
        }
        __syncthreads();
#pragma unroll
        for (int k = 0; k < 16; k++) {
            float4 a0 = *(const float4*)&As[k][ty * 8];
            float4 a1 = *(const float4*)&As[k][ty * 8 + 4];
            float4 b0 = *(const float4*)&Bs[k][tx * 8];
            float4 b1 = *(const float4*)&Bs[k][tx * 8 + 4];
            float av[8] = {a0.x, a0.y, a0.z, a0.w, a1.x, a1.y, a1.z, a1.w};
            float bv[8] = {b0.x, b0.y, b0.z, b0.w, b1.x, b1.y, b1.z, b1.w};
#pragma unroll
            for (int i = 0; i < 8; i++)
#pragma unroll
                for (int j = 0; j < 8; j++) acc[i][j] += av[i] * bv[j];
        }
        __syncthreads();
    }

    if (omode == 3) {
#pragma unroll
        for (int i = 0; i < 8; i++) {
            int r = m0 + ty * 8 + i;
#pragma unroll
            for (int j = 0; j < 8; j++) {
                int o = n0 + tx * 8 + j;
                Yext[(size_t)r * HIDD + o] = acc[i][j] + bias[o];
            }
        }
    } else {
        float* dst = (omode == 0) ? g_Q : (omode == 1) ? g_K : g_V;
#pragma unroll
        for (int i = 0; i < 8; i++) {
            int r = m0 + ty * 8 + i;
            int l = r >> 1, bb = r & 1;           // r = l*B + b, B=2
#pragma unroll
            for (int j = 0; j < 8; j++) {
                int o = n0 + tx * 8 + j;
                int h = o >> 6, d = o & 63;
                dst[(((size_t)(bb * HEADS + h)) * LSEQ + l) * DH + d] = acc[i][j] + bias[o];
            }
        }
    }
}

// ---------------- flash attention, fp32, 64q x 64k tiles ----------------
// 256 threads = 16x16 grid: ty -> 4 query rows, tx -> 4 key cols (S phase)
// and tx -> 4 output dims (PV phase). Smem layouts chosen so all LDS.128
// are conflict-free or broadcast.
#define SPITCH 68
__global__ __launch_bounds__(256) void attn_kernel(const float* __restrict__ tao) {
    extern __shared__ float sm[];
    float* Qt = sm;                      // [DH][SPITCH] transposed, pre-scaled
    float* Kt = Qt + 64 * SPITCH;        // [DH][SPITCH] transposed
    float* Vs = Kt + 64 * SPITCH;        // [64k][SPITCH]
    float* Ps = Vs + 64 * SPITCH;        // [64q][SPITCH]

    int bh = blockIdx.x;
    int b = bh >> 4, h = bh & 15;
    int q0 = blockIdx.y * 64;
    int tid = threadIdx.x;
    int tx = tid & 15, ty = tid >> 4;
    int qy = ty * 4, kx = tx * 4;        // kx doubles as dx in PV phase

    float tt = tao[h];
    float nh = -0.5f / (tt * tt * tt * tt);
    const float SCALE = 0.125f;          // DH^-0.5

    size_t base = ((size_t)(b * HEADS + h)) * LSEQ * DH;

    // load Q tile transposed + pre-scaled
    for (int i = tid; i < 1024; i += 256) {
        int r = i >> 4, d0 = (i & 15) << 2;
        float4 v = *(const float4*)(g_Q + base + (size_t)(q0 + r) * DH + d0);
        Qt[(d0 + 0) * SPITCH + r] = v.x * SCALE;
        Qt[(d0 + 1) * SPITCH + r] = v.y * SCALE;
        Qt[(d0 + 2) * SPITCH + r] = v.z * SCALE;
        Qt[(d0 + 3) * SPITCH + r] = v.w * SCALE;
    }

    float m[4], l[4], acc[4][4];
#pragma unroll
    for (int i = 0; i < 4; i++) {
        m[i] = -3.0e38f; l[i] = 0.0f;
#pragma unroll
        for (int j = 0; j < 4; j++) acc[i][j] = 0.0f;
    }

    for (int k0 = 0; k0 < LSEQ; k0 += 64) {
        __syncthreads();   // previous tile's Ps/Vs readers done (also covers Qt on iter 0)
        for (int i = tid; i < 1024; i += 256) {
            int r = i >> 4, d0 = (i & 15) << 2;
            float4 kv = *(const float4*)(g_K + base + (size_t)(k0 + r) * DH + d0);
            Kt[(d0 + 0) * SPITCH + r] = kv.x;
            Kt[(d0 + 1) * SPITCH + r] = kv.y;
            Kt[(d0 + 2) * SPITCH + r] = kv.z;
            Kt[(d0 + 3) * SPITCH + r] = kv.w;
            float4 vv = *(const float4*)(g_V + base + (size_t)(k0 + r) * DH + d0);
            *(float4*)&Vs[r * SPITCH + d0] = vv;
        }
        __syncthreads();

        // S = (Q*scale) @ K^T  (outer-product over d)
        float s[4][4];
#pragma unroll
        for (int i = 0; i < 4; i++)
#pragma unroll
            for (int j = 0; j < 4; j++) s[i][j] = 0.0f;
#pragma unroll 8
        for (int d = 0; d < 64; d++) {
            float4 qv = *(const float4*)&Qt[d * SPITCH + qy];
            float4 kv = *(const float4*)&Kt[d * SPITCH + kx];
            float qa[4] = {qv.x, qv.y, qv.z, qv.w};
            float ka[4] = {kv.x, kv.y, kv.z, kv.w};
#pragma unroll
            for (int i = 0; i < 4; i++)
#pragma unroll
                for (int j = 0; j < 4; j++) s[i][j] += qa[i] * ka[j];
        }

        // gaussian positional bias + key mask
        float mbj[4];
#pragma unroll
        for (int j = 0; j < 4; j++) mbj[j] = g_mb[b * LSEQ + k0 + kx + j];
#pragma unroll
        for (int i = 0; i < 4; i++) {
            int qg = q0 + qy + i;
#pragma unroll
            for (int j = 0; j < 4; j++) {
                float diff = (float)(qg - (k0 + kx + j));
                s[i][j] += diff * diff * nh + mbj[j];
            }
        }

        // online softmax update (row reductions across the 16 tx lanes)
#pragma unroll
        for (int i = 0; i < 4; i++) {
            float mt = fmaxf(fmaxf(s[i][0], s[i][1]), fmaxf(s[i][2], s[i][3]));
#pragma unroll
            for (int o = 1; o < 16; o <<= 1)
                mt = fmaxf(mt, __shfl_xor_sync(0xffffffffu, mt, o));
            float mn = fmaxf(m[i], mt);
            float c = __expf(m[i] - mn);
            float rs = 0.0f;
#pragma unroll
            for (int j = 0; j < 4; j++) {
                s[i][j] = __expf(s[i][j] - mn);
                rs += s[i][j];
            }
#pragma unroll
            for (int o = 1; o < 16; o <<= 1)
                rs += __shfl_xor_sync(0xffffffffu, rs, o);
            l[i] = l[i] * c + rs;
            m[i] = mn;
#pragma unroll
            for (int j = 0; j < 4; j++) {
                acc[i][j] *= c;
                Ps[(qy + i) * SPITCH + kx + j] = s[i][j];
            }
        }
        __syncthreads();

        // acc += P @ V
#pragma unroll 8
        for (int k = 0; k < 64; k++) {
            float4 vv = *(const float4*)&Vs[k * SPITCH + kx];
            float va[4] = {vv.x, vv.y, vv.z, vv.w};
#pragma unroll
            for (int i = 0; i < 4; i++) {
                float p = Ps[(qy + i) * SPITCH + k];
#pragma unroll
                for (int j = 0; j < 4; j++) acc[i][j] += p * va[j];
            }
        }
    }

    // write context: row r = q*B + b, col = h*64 + d
#pragma unroll
    for (int i = 0; i < 4; i++) {
        float inv = 1.0f / l[i];
        int qg = q0 + qy + i;
#pragma unroll
        for (int j = 0; j < 4; j++)
            g_ctx[((size_t)qg * BB + b) * HIDD + h * DH + kx + j] = acc[i][j] * inv;
    }
}

// ---------------- launcher ----------------
// Inputs are classified by element count (robust to metadata ordering):
//   L*B*HID = 4194304 -> activations (q, k, v in order of appearance)
//   HID*HID = 1048576 -> weights     (wq, wk, wv, wfc in order)
//   B*L     =    4096 -> mask
//   HID     =    1024 -> biases      (bq, bk, bv, bfc in order)
//   HEADS   =      16 -> tao
extern "C" void kernel_launch(void* const* d_in, const int* in_sizes, int n_in,
                              void* d_out, int out_size) {
    const float* act[3] = {nullptr, nullptr, nullptr};
    const float* W[4]   = {nullptr, nullptr, nullptr, nullptr};
    const float* Bv[4]  = {nullptr, nullptr, nullptr, nullptr};
    const float* tao = nullptr;
    const unsigned char* mask = nullptr;
    int na = 0, nw = 0, nb = 0;
    for (int i = 0; i < n_in; i++) {
        long s = in_sizes[i];
        if (s == (long)LSEQ * BB * HIDD)      { if (na < 3) act[na++] = (const float*)d_in[i]; }
        else if (s == (long)HIDD * HIDD)      { if (nw < 4) W[nw++]   = (const float*)d_in[i]; }
        else if (s == (long)HIDD)             { if (nb < 4) Bv[nb++]  = (const float*)d_in[i]; }
        else if (s == (long)HEADS)            { tao = (const float*)d_in[i]; }
        else if (s == (long)BB * LSEQ)        { mask = (const unsigned char*)d_in[i]; }
    }
    float* out = (float*)d_out;

    prep_mask<<<1, 1024>>>(mask);

    dim3 gg(HIDD / 128, NTOK / 128);
    gemm_wt<<<gg, 256>>>(act[0], W[0], Bv[0], nullptr, 0, 0);   // Q = q @ wq^T + bq
    gemm_wt<<<gg, 256>>>(act[1], W[1], Bv[1], nullptr, 0, 1);   // K = k @ wk^T + bk
    gemm_wt<<<gg, 256>>>(act[2], W[2], Bv[2], nullptr, 0, 2);   // V = v @ wv^T + bv

    const int SMEM = 4 * 64 * SPITCH * (int)sizeof(float);   // 69632 B
    cudaFuncSetAttribute(attn_kernel, cudaFuncAttributeMaxDynamicSharedMemorySize, SMEM);
    attn_kernel<<<dim3(BB * HEADS, LSEQ / 64), 256, SMEM>>>(tao);

    gemm_wt<<<gg, 256>>>(nullptr, W[3], Bv[3], out, 1, 3);      // out = ctx @ wfc^T + bfc
}

// round 11
// speedup vs baseline: 1.4323x; 1.4323x over previous
#include <cuda_runtime.h>
#include <cuda_bf16.h>
#include <cstdint>

#define LSEQ 2048
#define BB 2
#define HIDD 1024
#define HEADS 16
#define DH 64
#define NTOK (LSEQ*BB)

// ---------------- scratch (device globals; no allocation allowed) ----------------
__device__ float g_Q[(size_t)BB*HEADS*LSEQ*DH];
__device__ float g_K[(size_t)BB*HEADS*LSEQ*DH];
__device__ float g_V[(size_t)BB*HEADS*LSEQ*DH];
__device__ float g_ctx[(size_t)NTOK*HIDD];
__device__ float g_mb[BB*LSEQ];
// bf16 split buffers (reused sequentially across the 4 GEMMs)
__device__ __align__(16) __nv_bfloat16 g_Xhi[(size_t)NTOK*HIDD];
__device__ __align__(16) __nv_bfloat16 g_Xlo[(size_t)NTOK*HIDD];
__device__ __align__(16) __nv_bfloat16 g_Whi[(size_t)HIDD*HIDD];
__device__ __align__(16) __nv_bfloat16 g_Wlo[(size_t)HIDD*HIDD];

// ---------------- mask normalization (dtype-robust) ----------------
__global__ void prep_mask(const unsigned char* __restrict__ mraw) {
    __shared__ int s_u8, s_f32;
    int t = threadIdx.x;
    if (t == 0) { s_u8 = 0; s_f32 = 0; }
    __syncthreads();
    int u8 = 0, f32 = 0;
    for (int i = t; i < BB*LSEQ; i += blockDim.x) {
        unsigned char v = mraw[i];
        if (v > 1) f32 = 1;
        if ((i & 3) != 0 && v) u8 = 1;
    }
    if (u8)  atomicOr(&s_u8, 1);
    if (f32) atomicOr(&s_f32, 1);
    __syncthreads();
    int is_f32 = s_f32, is_u8 = s_u8;
    for (int i = t; i < BB*LSEQ; i += blockDim.x) {
        bool m;
        if (is_f32)      m = (((const float*)mraw)[i] != 0.0f);
        else if (is_u8)  m = (mraw[i] != 0);
        else             m = (((const int*)mraw)[i] != 0);
        g_mb[i] = m ? -1e30f : 0.0f;
    }
}

// ---------------- f32 -> (bf16 hi, bf16 lo) split ----------------
// srcsel 1: source is g_ctx. dstsel 0: write g_Xhi/g_Xlo, 1: write g_Whi/g_Wlo.
// All device-global references stay in DEVICE code (host must not take their address).
__global__ __launch_bounds__(256) void split_bf16(
    const float* __restrict__ srcp, int n, int srcsel, int dstsel)
{
    const float* src = srcsel ? g_ctx : srcp;
    __nv_bfloat16* hi = dstsel ? g_Whi : g_Xhi;
    __nv_bfloat16* lo = dstsel ? g_Wlo : g_Xlo;
    int i = (blockIdx.x * blockDim.x + threadIdx.x) * 4;
    if (i >= n) return;
    float4 v = *(const float4*)(src + i);
    __nv_bfloat16 h0 = __float2bfloat16(v.x);
    __nv_bfloat16 h1 = __float2bfloat16(v.y);
    __nv_bfloat16 h2 = __float2bfloat16(v.z);
    __nv_bfloat16 h3 = __float2bfloat16(v.w);
    __nv_bfloat16 l0 = __float2bfloat16(v.x - __bfloat162float(h0));
    __nv_bfloat16 l1 = __float2bfloat16(v.y - __bfloat162float(h1));
    __nv_bfloat16 l2 = __float2bfloat16(v.z - __bfloat162float(h2));
    __nv_bfloat16 l3 = __float2bfloat16(v.w - __bfloat162float(h3));
    *(__nv_bfloat162*)(hi + i)     = __nv_bfloat162(h0, h1);
    *(__nv_bfloat162*)(hi + i + 2) = __nv_bfloat162(h2, h3);
    *(__nv_bfloat162*)(lo + i)     = __nv_bfloat162(l0, l1);
    *(__nv_bfloat162*)(lo + i + 2) = __nv_bfloat162(l2, l3);
}

// ---------------- tensor-core GEMM: Y = X @ W^T + bias (3xBF16 split) ----------------
// X splits in g_Xhi/g_Xlo [M=4096, K=1024]; W splits in g_Whi/g_Wlo [N=1024, K=1024].
// Both K-contiguous -> mma.sync m16n8k16 row.col directly.
// omode 0/1/2: scatter into g_Q/g_K/g_V [b][h][l][d]; omode 3: [r][o] into Yext.
__device__ __forceinline__ void mma16816(float* c, const uint32_t* a, const uint32_t* b) {
    asm volatile(
        "mma.sync.aligned.m16n8k16.row.col.f32.bf16.bf16.f32 "
        "{%0,%1,%2,%3}, {%4,%5,%6,%7}, {%8,%9}, {%0,%1,%2,%3};\n"
        : "+f"(c[0]), "+f"(c[1]), "+f"(c[2]), "+f"(c[3])
        : "r"(a[0]), "r"(a[1]), "r"(a[2]), "r"(a[3]), "r"(b[0]), "r"(b[1]));
}

#define GPITCH 40   // bf16 elements per smem row (32 data + 8 pad): conflict-free frag LDS

__global__ __launch_bounds__(256) void gemm_mma(
    const float* __restrict__ bias, float* __restrict__ Yext, int omode)
{
    __shared__ __align__(16) __nv_bfloat16 sAhi[128*GPITCH];
    __shared__ __align__(16) __nv_bfloat16 sAlo[128*GPITCH];
    __shared__ __align__(16) __nv_bfloat16 sBhi[128*GPITCH];
    __shared__ __align__(16) __nv_bfloat16 sBlo[128*GPITCH];

    int tid = threadIdx.x;
    int m0 = blockIdx.y * 128, n0 = blockIdx.x * 128;
    int lane = tid & 31, wid = tid >> 5;
    int wm = wid >> 2, wn = wid & 3;          // 2 x 4 warp grid, warp tile 64m x 32n
    int g = lane >> 2, t = lane & 3;

    // global staging: thread -> (row, 16-elem col chunk)
    int lrow = tid >> 1, lcol = (tid & 1) * 16;

    float c[4][4][4];
#pragma unroll
    for (int i = 0; i < 4; i++)
#pragma unroll
        for (int j = 0; j < 4; j++)
#pragma unroll
            for (int r = 0; r < 4; r++) c[i][j][r] = 0.0f;

    uint4 ra0, ra1, rl0, rl1, rw0, rw1, rv0, rv1;

    const size_t arow = (size_t)(m0 + lrow) * HIDD + lcol;
    const size_t wrow = (size_t)(n0 + lrow) * HIDD + lcol;

    // prologue load (k0 = 0)
    ra0 = *(const uint4*)(g_Xhi + arow);     ra1 = *(const uint4*)(g_Xhi + arow + 8);
    rl0 = *(const uint4*)(g_Xlo + arow);     rl1 = *(const uint4*)(g_Xlo + arow + 8);
    rw0 = *(const uint4*)(g_Whi + wrow);     rw1 = *(const uint4*)(g_Whi + wrow + 8);
    rv0 = *(const uint4*)(g_Wlo + wrow);     rv1 = *(const uint4*)(g_Wlo + wrow + 8);

    for (int it = 0; it < HIDD / 32; it++) {
        __syncthreads();
        int so = lrow * GPITCH + lcol;
        *(uint4*)&sAhi[so] = ra0;  *(uint4*)&sAhi[so + 8] = ra1;
        *(uint4*)&sAlo[so] = rl0;  *(uint4*)&sAlo[so + 8] = rl1;
        *(uint4*)&sBhi[so] = rw0;  *(uint4*)&sBhi[so + 8] = rw1;
        *(uint4*)&sBlo[so] = rv0;  *(uint4*)&sBlo[so + 8] = rv1;
        __syncthreads();

        if (it + 1 < HIDD / 32) {
            int k0 = (it + 1) * 32;
            ra0 = *(const uint4*)(g_Xhi + arow + k0); ra1 = *(const uint4*)(g_Xhi + arow + k0 + 8);
            rl0 = *(const uint4*)(g_Xlo + arow + k0); rl1 = *(const uint4*)(g_Xlo + arow + k0 + 8);
            rw0 = *(const uint4*)(g_Whi + wrow + k0); rw1 = *(const uint4*)(g_Whi + wrow + k0 + 8);
            rv0 = *(const uint4*)(g_Wlo + wrow + k0); rv1 = *(const uint4*)(g_Wlo + wrow + k0 + 8);
        }

#pragma unroll
        for (int ks = 0; ks < 2; ks++) {
            int kk = ks * 16 + t * 2;
            uint32_t ah[4][4], al[4][4], bh[4][2], bl[4][2];
#pragma unroll
            for (int mf = 0; mf < 4; mf++) {
                int r0 = (wm * 64 + mf * 16 + g) * GPITCH + kk;
                ah[mf][0] = *(const uint32_t*)&sAhi[r0];
                ah[mf][1] = *(const uint32_t*)&sAhi[r0 + 8 * GPITCH];
                ah[mf][2] = *(const uint32_t*)&sAhi[r0 + 8];
                ah[mf][3] = *(const uint32_t*)&sAhi[r0 + 8 * GPITCH + 8];
                al[mf][0] = *(const uint32_t*)&sAlo[r0];
                al[mf][1] = *(const uint32_t*)&sAlo[r0 + 8 * GPITCH];
                al[mf][2] = *(const uint32_t*)&sAlo[r0 + 8];
                al[mf][3] = *(const uint32_t*)&sAlo[r0 + 8 * GPITCH + 8];
            }
#pragma unroll
            for (int nf = 0; nf < 4; nf++) {
                int r0 = (wn * 32 + nf * 8 + g) * GPITCH + kk;
                bh[nf][0] = *(const uint32_t*)&sBhi[r0];
                bh[nf][1] = *(const uint32_t*)&sBhi[r0 + 8];
                bl[nf][0] = *(const uint32_t*)&sBlo[r0];
                bl[nf][1] = *(const uint32_t*)&sBlo[r0 + 8];
            }
#pragma unroll
            for (int mf = 0; mf < 4; mf++)
#pragma unroll
                for (int nf = 0; nf < 4; nf++) {
                    mma16816(c[mf][nf], ah[mf], bh[nf]);   // hi*hi
                    mma16816(c[mf][nf], al[mf], bh[nf]);   // lo*hi
                    mma16816(c[mf][nf], ah[mf], bl[nf]);   // hi*lo
                }
        }
    }

    // epilogue: c0=C[r][o], c1=C[r][o+1], c2=C[r+8][o], c3=C[r+8][o+1]
#pragma unroll
    for (int mf = 0; mf < 4; mf++) {
#pragma unroll
        for (int nf = 0; nf < 4; nf++) {
            int r = m0 + wm * 64 + mf * 16 + g;
            int o = n0 + wn * 32 + nf * 8 + t * 2;
            float b0 = bias[o], b1 = bias[o + 1];
            float v00 = c[mf][nf][0] + b0, v01 = c[mf][nf][1] + b1;
            float v10 = c[mf][nf][2] + b0, v11 = c[mf][nf][3] + b1;
            if (omode == 3) {
                *(float2*)&Yext[(size_t)r * HIDD + o]       = make_float2(v00, v01);
                *(float2*)&Yext[(size_t)(r + 8) * HIDD + o] = make_float2(v10, v11);
            } else {
                float* dst = (omode == 0) ? g_Q : (omode == 1) ? g_K : g_V;
                int h = o >> 6, d = o & 63;
                {
                    int l = r >> 1, bb = r & 1;
                    *(float2*)&dst[(((size_t)(bb * HEADS + h)) * LSEQ + l) * DH + d] = make_float2(v00, v01);
                }
                {
                    int r2 = r + 8;
                    int l = r2 >> 1, bb = r2 & 1;
                    *(float2*)&dst[(((size_t)(bb * HEADS + h)) * LSEQ + l) * DH + d] = make_float2(v10, v11);
                }
            }
        }
    }
}

// ---------------- flash attention, fp32, 64q x 64k tiles ----------------
#define SPITCH 68
__global__ __launch_bounds__(256) void attn_kernel(const float* __restrict__ tao) {
    extern __shared__ float sm[];
    float* Qt = sm;                      // [DH][SPITCH] transposed, pre-scaled
    float* Kt = Qt + 64 * SPITCH;        // [DH][SPITCH] transposed
    float* Vs = Kt + 64 * SPITCH;        // [64k][SPITCH]
    float* Ps = Vs + 64 * SPITCH;        // [64q][SPITCH]

    int bh = blockIdx.x;
    int b = bh >> 4, h = bh & 15;
    int q0 = blockIdx.y * 64;
    int tid = threadIdx.x;
    int tx = tid & 15, ty = tid >> 4;
    int qy = ty * 4, kx = tx * 4;

    float tt = tao[h];
    float nh = -0.5f / (tt * tt * tt * tt);
    const float SCALE = 0.125f;          // DH^-0.5

    size_t base = ((size_t)(b * HEADS + h)) * LSEQ * DH;

    for (int i = tid; i < 1024; i += 256) {
        int r = i >> 4, d0 = (i & 15) << 2;
        float4 v = *(const float4*)(g_Q + base + (size_t)(q0 + r) * DH + d0);
        Qt[(d0 + 0) * SPITCH + r] = v.x * SCALE;
        Qt[(d0 + 1) * SPITCH + r] = v.y * SCALE;
        Qt[(d0 + 2) * SPITCH + r] = v.z * SCALE;
        Qt[(d0 + 3) * SPITCH + r] = v.w * SCALE;
    }

    float m[4], l[4], acc[4][4];
#pragma unroll
    for (int i = 0; i < 4; i++) {
        m[i] = -3.0e38f; l[i] = 0.0f;
#pragma unroll
        for (int j = 0; j < 4; j++) acc[i][j] = 0.0f;
    }

    for (int k0 = 0; k0 < LSEQ; k0 += 64) {
        __syncthreads();
        for (int i = tid; i < 1024; i += 256) {
            int r = i >> 4, d0 = (i & 15) << 2;
            float4 kv = *(const float4*)(g_K + base + (size_t)(k0 + r) * DH + d0);
            Kt[(d0 + 0) * SPITCH + r] = kv.x;
            Kt[(d0 + 1) * SPITCH + r] = kv.y;
            Kt[(d0 + 2) * SPITCH + r] = kv.z;
            Kt[(d0 + 3) * SPITCH + r] = kv.w;
            float4 vv = *(const float4*)(g_V + base + (size_t)(k0 + r) * DH + d0);
            *(float4*)&Vs[r * SPITCH + d0] = vv;
        }
        __syncthreads();

        float s[4][4];
#pragma unroll
        for (int i = 0; i < 4; i++)
#pragma unroll
            for (int j = 0; j < 4; j++) s[i][j] = 0.0f;
#pragma unroll 8
        for (int d = 0; d < 64; d++) {
            float4 qv = *(const float4*)&Qt[d * SPITCH + qy];
            float4 kv = *(const float4*)&Kt[d * SPITCH + kx];
            float qa[4] = {qv.x, qv.y, qv.z, qv.w};
            float ka[4] = {kv.x, kv.y, kv.z, kv.w};
#pragma unroll
            for (int i = 0; i < 4; i++)
#pragma unroll
                for (int j = 0; j < 4; j++) s[i][j] += qa[i] * ka[j];
        }

        float mbj[4];
#pragma unroll
        for (int j = 0; j < 4; j++) mbj[j] = g_mb[b * LSEQ + k0 + kx + j];
#pragma unroll
        for (int i = 0; i < 4; i++) {
            int qg = q0 + qy + i;
#pragma unroll
            for (int j = 0; j < 4; j++) {
                float diff = (float)(qg - (k0 + kx + j));
                s[i][j] += diff * diff * nh + mbj[j];
            }
        }

#pragma unroll
        for (int i = 0; i < 4; i++) {
            float mt = fmaxf(fmaxf(s[i][0], s[i][1]), fmaxf(s[i][2], s[i][3]));
#pragma unroll
            for (int o = 1; o < 16; o <<= 1)
                mt = fmaxf(mt, __shfl_xor_sync(0xffffffffu, mt, o));
            float mn = fmaxf(m[i], mt);
            float cc = __expf(m[i] - mn);
            float rs = 0.0f;
#pragma unroll
            for (int j = 0; j < 4; j++) {
                s[i][j] = __expf(s[i][j] - mn);
                rs += s[i][j];
            }
#pragma unroll
            for (int o = 1; o < 16; o <<= 1)
                rs += __shfl_xor_sync(0xffffffffu, rs, o);
            l[i] = l[i] * cc + rs;
            m[i] = mn;
#pragma unroll
            for (int j = 0; j < 4; j++) {
                acc[i][j] *= cc;
                Ps[(qy + i) * SPITCH + kx + j] = s[i][j];
            }
        }
        __syncthreads();

#pragma unroll 8
        for (int k = 0; k < 64; k++) {
            float4 vv = *(const float4*)&Vs[k * SPITCH + kx];
            float va[4] = {vv.x, vv.y, vv.z, vv.w};
#pragma unroll
            for (int i = 0; i < 4; i++) {
                float p = Ps[(qy + i) * SPITCH + k];
#pragma unroll
                for (int j = 0; j < 4; j++) acc[i][j] += p * va[j];
            }
        }
    }

#pragma unroll
    for (int i = 0; i < 4; i++) {
        float inv = 1.0f / l[i];
        int qg = q0 + qy + i;
#pragma unroll
        for (int j = 0; j < 4; j++)
            g_ctx[((size_t)qg * BB + b) * HIDD + h * DH + kx + j] = acc[i][j] * inv;
    }
}

// ---------------- launcher ----------------
// Inputs classified by element count (robust to metadata ordering):
//   4194304 -> activations (q, k, v)   1048576 -> weights (wq, wk, wv, wfc)
//   4096 -> mask   1024 -> biases (bq, bk, bv, bfc)   16 -> tao
extern "C" void kernel_launch(void* const* d_in, const int* in_sizes, int n_in,
                              void* d_out, int out_size) {
    const float* act[3] = {nullptr, nullptr, nullptr};
    const float* W[4]   = {nullptr, nullptr, nullptr, nullptr};
    const float* Bv[4]  = {nullptr, nullptr, nullptr, nullptr};
    const float* tao = nullptr;
    const unsigned char* mask = nullptr;
    int na = 0, nw = 0, nb = 0;
    for (int i = 0; i < n_in; i++) {
        long s = in_sizes[i];
        if (s == (long)LSEQ * BB * HIDD)      { if (na < 3) act[na++] = (const float*)d_in[i]; }
        else if (s == (long)HIDD * HIDD)      { if (nw < 4) W[nw++]   = (const float*)d_in[i]; }
        else if (s == (long)HIDD)             { if (nb < 4) Bv[nb++]  = (const float*)d_in[i]; }
        else if (s == (long)HEADS)            { tao = (const float*)d_in[i]; }
        else if (s == (long)BB * LSEQ)        { mask = (const unsigned char*)d_in[i]; }
    }
    float* out = (float*)d_out;

    prep_mask<<<1, 1024>>>(mask);

    const int NACT = NTOK * HIDD, NW = HIDD * HIDD;
    dim3 gg(HIDD / 128, NTOK / 128);

    // Q/K/V projections on tensor cores
    for (int p = 0; p < 3; p++) {
        split_bf16<<<NACT / 1024, 256>>>(act[p], NACT, 0, 0);  // -> g_Xhi/g_Xlo
        split_bf16<<<NW / 1024, 256>>>(W[p], NW, 0, 1);        // -> g_Whi/g_Wlo
        gemm_mma<<<gg, 256>>>(Bv[p], nullptr, p);
    }

    const int SMEM = 4 * 64 * SPITCH * (int)sizeof(float);   // 69632 B
    cudaFuncSetAttribute(attn_kernel, cudaFuncAttributeMaxDynamicSharedMemorySize, SMEM);
    attn_kernel<<<dim3(BB * HEADS, LSEQ / 64), 256, SMEM>>>(tao);

    // FC projection
    split_bf16<<<NACT / 1024, 256>>>(nullptr, NACT, 1, 0);     // from g_ctx -> g_Xhi/g_Xlo
    split_bf16<<<NW / 1024, 256>>>(W[3], NW, 0, 1);            // -> g_Whi/g_Wlo
    gemm_mma<<<gg, 256>>>(Bv[3], out, 3);
}

// round 12
// speedup vs baseline: 2.4291x; 1.6959x over previous
#include <cuda_runtime.h>
#include <cuda_bf16.h>
#include <cstdint>

#define LSEQ 2048
#define BB 2
#define HIDD 1024
#define HEADS 16
#define DH 64
#define NTOK (LSEQ*BB)

// ---------------- scratch (device globals; no allocation allowed) ----------------
__device__ float g_mb[BB*LSEQ];
// bf16 split buffers
__device__ __align__(16) __nv_bfloat16 g_Xhi[(size_t)NTOK*HIDD];
__device__ __align__(16) __nv_bfloat16 g_Xlo[(size_t)NTOK*HIDD];
__device__ __align__(16) __nv_bfloat16 g_Whi[(size_t)HIDD*HIDD];
__device__ __align__(16) __nv_bfloat16 g_Wlo[(size_t)HIDD*HIDD];
// Q/K: [b*16+h][l][d], V: [b*16+h][d][l] (pre-transposed for PV mma)
__device__ __align__(16) __nv_bfloat16 g_Qhi[(size_t)BB*HEADS*LSEQ*DH];
__device__ __align__(16) __nv_bfloat16 g_Qlo[(size_t)BB*HEADS*LSEQ*DH];
__device__ __align__(16) __nv_bfloat16 g_Khi[(size_t)BB*HEADS*LSEQ*DH];
__device__ __align__(16) __nv_bfloat16 g_Klo[(size_t)BB*HEADS*LSEQ*DH];
__device__ __align__(16) __nv_bfloat16 g_Vhi[(size_t)BB*HEADS*LSEQ*DH];
__device__ __align__(16) __nv_bfloat16 g_Vlo[(size_t)BB*HEADS*LSEQ*DH];

// ---------------- helpers ----------------
__device__ __forceinline__ void split1(float v, __nv_bfloat16& hi, __nv_bfloat16& lo) {
    hi = __float2bfloat16(v);
    lo = __float2bfloat16(v - __bfloat162float(hi));
}
__device__ __forceinline__ void split2u(float a, float b, uint32_t& hi, uint32_t& lo) {
    __nv_bfloat16 ha, la, hb, lb;
    split1(a, ha, la); split1(b, hb, lb);
    __nv_bfloat162 H(ha, hb), L(la, lb);
    hi = *reinterpret_cast<uint32_t*>(&H);
    lo = *reinterpret_cast<uint32_t*>(&L);
}
__device__ __forceinline__ void mma16816(float* c, const uint32_t* a, const uint32_t* b) {
    asm volatile(
        "mma.sync.aligned.m16n8k16.row.col.f32.bf16.bf16.f32 "
        "{%0,%1,%2,%3}, {%4,%5,%6,%7}, {%8,%9}, {%0,%1,%2,%3};\n"
        : "+f"(c[0]), "+f"(c[1]), "+f"(c[2]), "+f"(c[3])
        : "r"(a[0]), "r"(a[1]), "r"(a[2]), "r"(a[3]), "r"(b[0]), "r"(b[1]));
}

// ---------------- mask normalization (dtype-robust) ----------------
__global__ void prep_mask(const unsigned char* __restrict__ mraw) {
    __shared__ int s_u8, s_f32;
    int t = threadIdx.x;
    if (t == 0) { s_u8 = 0; s_f32 = 0; }
    __syncthreads();
    int u8 = 0, f32 = 0;
    for (int i = t; i < BB*LSEQ; i += blockDim.x) {
        unsigned char v = mraw[i];
        if (v > 1) f32 = 1;
        if ((i & 3) != 0 && v) u8 = 1;
    }
    if (u8)  atomicOr(&s_u8, 1);
    if (f32) atomicOr(&s_f32, 1);
    __syncthreads();
    int is_f32 = s_f32, is_u8 = s_u8;
    for (int i = t; i < BB*LSEQ; i += blockDim.x) {
        bool m;
        if (is_f32)      m = (((const float*)mraw)[i] != 0.0f);
        else if (is_u8)  m = (mraw[i] != 0);
        else             m = (((const int*)mraw)[i] != 0);
        g_mb[i] = m ? -1e30f : 0.0f;
    }
}

// ---------------- f32 -> (bf16 hi, bf16 lo) split ----------------
__global__ __launch_bounds__(256) void split_bf16(
    const float* __restrict__ src, int n, int dstsel)
{
    __nv_bfloat16* hi = dstsel ? g_Whi : g_Xhi;
    __nv_bfloat16* lo = dstsel ? g_Wlo : g_Xlo;
    int i = (blockIdx.x * blockDim.x + threadIdx.x) * 4;
    if (i >= n) return;
    float4 v = *(const float4*)(src + i);
    uint32_t h0, l0, h1, l1;
    split2u(v.x, v.y, h0, l0);
    split2u(v.z, v.w, h1, l1);
    *(uint32_t*)(hi + i)     = h0;  *(uint32_t*)(hi + i + 2) = h1;
    *(uint32_t*)(lo + i)     = l0;  *(uint32_t*)(lo + i + 2) = l1;
}

// ---------------- tensor-core GEMM: Y = X @ W^T + bias (3xBF16 split) ----------------
// omode 0: Q (pre-scaled by 0.125, split -> g_Qhi/lo [bh][l][d])
// omode 1: K (split -> g_Khi/lo [bh][l][d])
// omode 2: V (split -> g_Vhi/lo [bh][d][l] TRANSPOSED)
// omode 3: f32 [r][o] into Yext (final FC -> d_out)
#define GPITCH 40

__global__ __launch_bounds__(256) void gemm_mma(
    const float* __restrict__ bias, float* __restrict__ Yext, int omode)
{
    __shared__ __align__(16) __nv_bfloat16 sAhi[128*GPITCH];
    __shared__ __align__(16) __nv_bfloat16 sAlo[128*GPITCH];
    __shared__ __align__(16) __nv_bfloat16 sBhi[128*GPITCH];
    __shared__ __align__(16) __nv_bfloat16 sBlo[128*GPITCH];

    int tid = threadIdx.x;
    int m0 = blockIdx.y * 128, n0 = blockIdx.x * 128;
    int lane = tid & 31, wid = tid >> 5;
    int wm = wid >> 2, wn = wid & 3;
    int g = lane >> 2, t = lane & 3;
    int lrow = tid >> 1, lcol = (tid & 1) * 16;

    float c[4][4][4];
#pragma unroll
    for (int i = 0; i < 4; i++)
#pragma unroll
        for (int j = 0; j < 4; j++)
#pragma unroll
            for (int r = 0; r < 4; r++) c[i][j][r] = 0.0f;

    uint4 ra0, ra1, rl0, rl1, rw0, rw1, rv0, rv1;
    const size_t arow = (size_t)(m0 + lrow) * HIDD + lcol;
    const size_t wrow = (size_t)(n0 + lrow) * HIDD + lcol;

    ra0 = *(const uint4*)(g_Xhi + arow);     ra1 = *(const uint4*)(g_Xhi + arow + 8);
    rl0 = *(const uint4*)(g_Xlo + arow);     rl1 = *(const uint4*)(g_Xlo + arow + 8);
    rw0 = *(const uint4*)(g_Whi + wrow);     rw1 = *(const uint4*)(g_Whi + wrow + 8);
    rv0 = *(const uint4*)(g_Wlo + wrow);     rv1 = *(const uint4*)(g_Wlo + wrow + 8);

    for (int it = 0; it < HIDD / 32; it++) {
        __syncthreads();
        int so = lrow * GPITCH + lcol;
        *(uint4*)&sAhi[so] = ra0;  *(uint4*)&sAhi[so + 8] = ra1;
        *(uint4*)&sAlo[so] = rl0;  *(uint4*)&sAlo[so + 8] = rl1;
        *(uint4*)&sBhi[so] = rw0;  *(uint4*)&sBhi[so + 8] = rw1;
        *(uint4*)&sBlo[so] = rv0;  *(uint4*)&sBlo[so + 8] = rv1;
        __syncthreads();

        if (it + 1 < HIDD / 32) {
            int k0 = (it + 1) * 32;
            ra0 = *(const uint4*)(g_Xhi + arow + k0); ra1 = *(const uint4*)(g_Xhi + arow + k0 + 8);
            rl0 = *(const uint4*)(g_Xlo + arow + k0); rl1 = *(const uint4*)(g_Xlo + arow + k0 + 8);
            rw0 = *(const uint4*)(g_Whi + wrow + k0); rw1 = *(const uint4*)(g_Whi + wrow + k0 + 8);
            rv0 = *(const uint4*)(g_Wlo + wrow + k0); rv1 = *(const uint4*)(g_Wlo + wrow + k0 + 8);
        }

#pragma unroll
        for (int ks = 0; ks < 2; ks++) {
            int kk = ks * 16 + t * 2;
            uint32_t ah[4][4], al[4][4], bh[4][2], bl[4][2];
#pragma unroll
            for (int mf = 0; mf < 4; mf++) {
                int r0 = (wm * 64 + mf * 16 + g) * GPITCH + kk;
                ah[mf][0] = *(const uint32_t*)&sAhi[r0];
                ah[mf][1] = *(const uint32_t*)&sAhi[r0 + 8 * GPITCH];
                ah[mf][2] = *(const uint32_t*)&sAhi[r0 + 8];
                ah[mf][3] = *(const uint32_t*)&sAhi[r0 + 8 * GPITCH + 8];
                al[mf][0] = *(const uint32_t*)&sAlo[r0];
                al[mf][1] = *(const uint32_t*)&sAlo[r0 + 8 * GPITCH];
                al[mf][2] = *(const uint32_t*)&sAlo[r0 + 8];
                al[mf][3] = *(const uint32_t*)&sAlo[r0 + 8 * GPITCH + 8];
            }
#pragma unroll
            for (int nf = 0; nf < 4; nf++) {
                int r0 = (wn * 32 + nf * 8 + g) * GPITCH + kk;
                bh[nf][0] = *(const uint32_t*)&sBhi[r0];
                bh[nf][1] = *(const uint32_t*)&sBhi[r0 + 8];
                bl[nf][0] = *(const uint32_t*)&sBlo[r0];
                bl[nf][1] = *(const uint32_t*)&sBlo[r0 + 8];
            }
#pragma unroll
            for (int mf = 0; mf < 4; mf++)
#pragma unroll
                for (int nf = 0; nf < 4; nf++) {
                    mma16816(c[mf][nf], ah[mf], bh[nf]);
                    mma16816(c[mf][nf], al[mf], bh[nf]);
                    mma16816(c[mf][nf], ah[mf], bl[nf]);
                }
        }
    }

    float qs = (omode == 0) ? 0.125f : 1.0f;   // fold DH^-0.5 into Q (exact pow2)
#pragma unroll
    for (int mf = 0; mf < 4; mf++) {
#pragma unroll
        for (int nf = 0; nf < 4; nf++) {
            int r = m0 + wm * 64 + mf * 16 + g;
            int o = n0 + wn * 32 + nf * 8 + t * 2;
            float b0 = bias[o], b1 = bias[o + 1];
            float v00 = c[mf][nf][0] + b0, v01 = c[mf][nf][1] + b1;
            float v10 = c[mf][nf][2] + b0, v11 = c[mf][nf][3] + b1;
            if (omode == 3) {
                *(float2*)&Yext[(size_t)r * HIDD + o]       = make_float2(v00, v01);
                *(float2*)&Yext[(size_t)(r + 8) * HIDD + o] = make_float2(v10, v11);
            } else {
                int h = o >> 6, d = o & 63;
                if (omode == 2) {   // V transposed [bh][d][l]
#pragma unroll
                    for (int rr = 0; rr < 2; rr++) {
                        int r2 = r + rr * 8;
                        int l = r2 >> 1, bb = r2 & 1;
                        size_t vb = ((size_t)((bb * HEADS + h) * DH + d)) * LSEQ + l;
                        __nv_bfloat16 hi, lo;
                        float va = rr ? v10 : v00, vbv = rr ? v11 : v01;
                        split1(va, hi, lo);  g_Vhi[vb] = hi;        g_Vlo[vb] = lo;
                        split1(vbv, hi, lo); g_Vhi[vb + LSEQ] = hi; g_Vlo[vb + LSEQ] = lo;
                    }
                } else {            // Q/K [bh][l][d]
                    __nv_bfloat16* dh = (omode == 0) ? g_Qhi : g_Khi;
                    __nv_bfloat16* dl = (omode == 0) ? g_Qlo : g_Klo;
#pragma unroll
                    for (int rr = 0; rr < 2; rr++) {
                        int r2 = r + rr * 8;
                        int l = r2 >> 1, bb = r2 & 1;
                        size_t qb = ((size_t)((bb * HEADS + h) * LSEQ + l)) * DH + d;
                        uint32_t hi, lo;
                        split2u((rr ? v10 : v00) * qs, (rr ? v11 : v01) * qs, hi, lo);
                        *(uint32_t*)&dh[qb] = hi;
                        *(uint32_t*)&dl[qb] = lo;
                    }
                }
            }
        }
    }
}

// ---------------- flash attention on tensor cores ----------------
// 128q x 64k tiles, 8 warps (each warp: 16 q-rows x full 64 k / 64 d).
// S = Q@K^T via 3-term bf16 mma; P kept in C-fragment registers, split to
// bf16 hi/lo in-register (C(m16n8) pairs == A(m16n16) fragment); O += P@V
// via 3-term mma with V pre-transposed in smem. Output written directly as
// g_Xhi/g_Xlo splits (FC GEMM input).
#define APITCH 72

__global__ __launch_bounds__(256) void attn_mma(const float* __restrict__ tao) {
    extern __shared__ __nv_bfloat16 smb[];
    __nv_bfloat16* sQh = smb;                    // [128 q][APITCH] cols=d
    __nv_bfloat16* sQl = sQh + 128 * APITCH;
    __nv_bfloat16* sKh = sQl + 128 * APITCH;     // [64 key][APITCH] cols=d
    __nv_bfloat16* sKl = sKh + 64 * APITCH;
    __nv_bfloat16* sVh = sKl + 64 * APITCH;      // [64 d][APITCH] cols=key
    __nv_bfloat16* sVl = sVh + 64 * APITCH;
    float* sMb = (float*)(sVl + 64 * APITCH);    // 64 mask-bias floats

    int bh = blockIdx.x;
    int b = bh >> 4, h = bh & 15;
    int q0 = blockIdx.y * 128;
    int tid = threadIdx.x;
    int lane = tid & 31, wid = tid >> 5;
    int g = lane >> 2, t = lane & 3;

    float tt = tao[h];
    float nh = -0.5f / (tt * tt * tt * tt);

    size_t qk_base = (size_t)bh * LSEQ * DH;   // Q/K: [bh][l][d]
    size_t v_base  = (size_t)bh * DH * LSEQ;   // V:   [bh][d][l]

    // load Q tile (128 x 64) hi+lo
    for (int i = tid; i < 1024; i += 256) {
        int row = i >> 3, d0 = (i & 7) * 8;
        size_t go = qk_base + (size_t)(q0 + row) * DH + d0;
        *(uint4*)&sQh[row * APITCH + d0] = *(const uint4*)(g_Qhi + go);
        *(uint4*)&sQl[row * APITCH + d0] = *(const uint4*)(g_Qlo + go);
    }

    float o[8][4];
#pragma unroll
    for (int i = 0; i < 8; i++)
#pragma unroll
        for (int j = 0; j < 4; j++) o[i][j] = 0.0f;
    float m0 = -3.0e38f, m1 = -3.0e38f, l0 = 0.0f, l1 = 0.0f;

    for (int k0 = 0; k0 < LSEQ; k0 += 64) {
        __syncthreads();
        for (int i = tid; i < 512; i += 256) {
            int row = i >> 3, d0 = (i & 7) * 8;
            size_t go = qk_base + (size_t)(k0 + row) * DH + d0;
            *(uint4*)&sKh[row * APITCH + d0] = *(const uint4*)(g_Khi + go);
            *(uint4*)&sKl[row * APITCH + d0] = *(const uint4*)(g_Klo + go);
            size_t vo = v_base + (size_t)row * LSEQ + k0 + d0;   // row=d, d0=key off
            *(uint4*)&sVh[row * APITCH + d0] = *(const uint4*)(g_Vhi + vo);
            *(uint4*)&sVl[row * APITCH + d0] = *(const uint4*)(g_Vlo + vo);
        }
        if (tid < 64) sMb[tid] = g_mb[b * LSEQ + k0 + tid];
        __syncthreads();

        // ---- S = Q@K^T (rows wid*16+g, +8; cols nf*8+2t, +1) ----
        float sc[8][4];
#pragma unroll
        for (int nf = 0; nf < 8; nf++)
#pragma unroll
            for (int j = 0; j < 4; j++) sc[nf][j] = 0.0f;

#pragma unroll
        for (int dc = 0; dc < 4; dc++) {
            int kk = dc * 16 + t * 2;
            int r0 = (wid * 16 + g) * APITCH + kk;
            uint32_t ah[4], al[4];
            ah[0] = *(const uint32_t*)&sQh[r0];
            ah[1] = *(const uint32_t*)&sQh[r0 + 8 * APITCH];
            ah[2] = *(const uint32_t*)&sQh[r0 + 8];
            ah[3] = *(const uint32_t*)&sQh[r0 + 8 * APITCH + 8];
            al[0] = *(const uint32_t*)&sQl[r0];
            al[1] = *(const uint32_t*)&sQl[r0 + 8 * APITCH];
            al[2] = *(const uint32_t*)&sQl[r0 + 8];
            al[3] = *(const uint32_t*)&sQl[r0 + 8 * APITCH + 8];
#pragma unroll
            for (int nf = 0; nf < 8; nf++) {
                int rb = (nf * 8 + g) * APITCH + kk;
                uint32_t bh2[2] = {*(const uint32_t*)&sKh[rb], *(const uint32_t*)&sKh[rb + 8]};
                uint32_t bl2[2] = {*(const uint32_t*)&sKl[rb], *(const uint32_t*)&sKl[rb + 8]};
                mma16816(sc[nf], ah, bh2);
                mma16816(sc[nf], al, bh2);
                mma16816(sc[nf], ah, bl2);
            }
        }

        // ---- gaussian bias + key mask ----
        int qr0 = q0 + wid * 16 + g, qr1 = qr0 + 8;
#pragma unroll
        for (int nf = 0; nf < 8; nf++) {
            int kc = k0 + nf * 8 + t * 2;
            float mb0 = sMb[nf * 8 + t * 2], mb1 = sMb[nf * 8 + t * 2 + 1];
            float d0 = (float)(qr0 - kc), d1 = (float)(qr0 - kc - 1);
            float d2 = (float)(qr1 - kc), d3 = (float)(qr1 - kc - 1);
            sc[nf][0] += d0 * d0 * nh + mb0;
            sc[nf][1] += d1 * d1 * nh + mb1;
            sc[nf][2] += d2 * d2 * nh + mb0;
            sc[nf][3] += d3 * d3 * nh + mb1;
        }

        // ---- online softmax (rows live on 4 lanes t=0..3) ----
        float mt0 = -3.0e38f, mt1 = -3.0e38f;
#pragma unroll
        for (int nf = 0; nf < 8; nf++) {
            mt0 = fmaxf(mt0, fmaxf(sc[nf][0], sc[nf][1]));
            mt1 = fmaxf(mt1, fmaxf(sc[nf][2], sc[nf][3]));
        }
        mt0 = fmaxf(mt0, __shfl_xor_sync(0xffffffffu, mt0, 1));
        mt0 = fmaxf(mt0, __shfl_xor_sync(0xffffffffu, mt0, 2));
        mt1 = fmaxf(mt1, __shfl_xor_sync(0xffffffffu, mt1, 1));
        mt1 = fmaxf(mt1, __shfl_xor_sync(0xffffffffu, mt1, 2));
        float mn0 = fmaxf(m0, mt0), mn1 = fmaxf(m1, mt1);
        float c0 = __expf(m0 - mn0), c1 = __expf(m1 - mn1);
        m0 = mn0; m1 = mn1;
        float rs0 = 0.0f, rs1 = 0.0f;
#pragma unroll
        for (int nf = 0; nf < 8; nf++) {
            sc[nf][0] = __expf(sc[nf][0] - mn0);
            sc[nf][1] = __expf(sc[nf][1] - mn0);
            sc[nf][2] = __expf(sc[nf][2] - mn1);
            sc[nf][3] = __expf(sc[nf][3] - mn1);
            rs0 += sc[nf][0] + sc[nf][1];
            rs1 += sc[nf][2] + sc[nf][3];
        }
        rs0 += __shfl_xor_sync(0xffffffffu, rs0, 1);
        rs0 += __shfl_xor_sync(0xffffffffu, rs0, 2);
        rs1 += __shfl_xor_sync(0xffffffffu, rs1, 1);
        rs1 += __shfl_xor_sync(0xffffffffu, rs1, 2);
        l0 = l0 * c0 + rs0;
        l1 = l1 * c1 + rs1;
#pragma unroll
        for (int dt = 0; dt < 8; dt++) {
            o[dt][0] *= c0; o[dt][1] *= c0;
            o[dt][2] *= c1; o[dt][3] *= c1;
        }

        // ---- O += P@V : P C-frags -> A-frags in registers ----
#pragma unroll
        for (int kc = 0; kc < 4; kc++) {
            uint32_t aph[4], apl[4];
            split2u(sc[2*kc][0],   sc[2*kc][1],   aph[0], apl[0]);   // row g,   k 16kc+2t
            split2u(sc[2*kc][2],   sc[2*kc][3],   aph[1], apl[1]);   // row g+8
            split2u(sc[2*kc+1][0], sc[2*kc+1][1], aph[2], apl[2]);   // row g,   k +8
            split2u(sc[2*kc+1][2], sc[2*kc+1][3], aph[3], apl[3]);   // row g+8
#pragma unroll
            for (int dt = 0; dt < 8; dt++) {
                int rb = (dt * 8 + g) * APITCH + kc * 16 + t * 2;
                uint32_t bh2[2] = {*(const uint32_t*)&sVh[rb], *(const uint32_t*)&sVh[rb + 8]};
                uint32_t bl2[2] = {*(const uint32_t*)&sVl[rb], *(const uint32_t*)&sVl[rb + 8]};
                mma16816(o[dt], aph, bh2);
                mma16816(o[dt], apl, bh2);
                mma16816(o[dt], aph, bl2);
            }
        }
    }

    // ---- epilogue: write ctx directly as bf16 splits (FC input) ----
    float inv0 = 1.0f / l0, inv1 = 1.0f / l1;
    int qg0 = q0 + wid * 16 + g;
    int r0 = qg0 * BB + b, r1 = (qg0 + 8) * BB + b;
#pragma unroll
    for (int dt = 0; dt < 8; dt++) {
        int oc = h * DH + dt * 8 + t * 2;
        uint32_t hi, lo;
        split2u(o[dt][0] * inv0, o[dt][1] * inv0, hi, lo);
        *(uint32_t*)&g_Xhi[(size_t)r0 * HIDD + oc] = hi;
        *(uint32_t*)&g_Xlo[(size_t)r0 * HIDD + oc] = lo;
        split2u(o[dt][2] * inv1, o[dt][3] * inv1, hi, lo);
        *(uint32_t*)&g_Xhi[(size_t)r1 * HIDD + oc] = hi;
        *(uint32_t*)&g_Xlo[(size_t)r1 * HIDD + oc] = lo;
    }
}

// ---------------- launcher ----------------
// Inputs classified by element count (robust to metadata ordering):
//   4194304 -> activations (q, k, v)   1048576 -> weights (wq, wk, wv, wfc)
//   4096 -> mask   1024 -> biases (bq, bk, bv, bfc)   16 -> tao
extern "C" void kernel_launch(void* const* d_in, const int* in_sizes, int n_in,
                              void* d_out, int out_size) {
    const float* act[3] = {nullptr, nullptr, nullptr};
    const float* W[4]   = {nullptr, nullptr, nullptr, nullptr};
    const float* Bv[4]  = {nullptr, nullptr, nullptr, nullptr};
    const float* tao = nullptr;
    const unsigned char* mask = nullptr;
    int na = 0, nw = 0, nb = 0;
    for (int i = 0; i < n_in; i++) {
        long s = in_sizes[i];
        if (s == (long)LSEQ * BB * HIDD)      { if (na < 3) act[na++] = (const float*)d_in[i]; }
        else if (s == (long)HIDD * HIDD)      { if (nw < 4) W[nw++]   = (const float*)d_in[i]; }
        else if (s == (long)HIDD)             { if (nb < 4) Bv[nb++]  = (const float*)d_in[i]; }
        else if (s == (long)HEADS)            { tao = (const float*)d_in[i]; }
        else if (s == (long)BB * LSEQ)        { mask = (const unsigned char*)d_in[i]; }
    }
    float* out = (float*)d_out;

    prep_mask<<<1, 1024>>>(mask);

    const int NACT = NTOK * HIDD, NW = HIDD * HIDD;
    dim3 gg(HIDD / 128, NTOK / 128);

    // Q/K/V projections (epilogue emits bf16 splits in attention layouts)
    for (int p = 0; p < 3; p++) {
        split_bf16<<<NACT / 1024, 256>>>(act[p], NACT, 0);  // -> g_Xhi/g_Xlo
        split_bf16<<<NW / 1024, 256>>>(W[p], NW, 1);        // -> g_Whi/g_Wlo
        gemm_mma<<<gg, 256>>>(Bv[p], nullptr, p);
    }

    // attention (writes g_Xhi/g_Xlo = split ctx, the FC input)
    const int ASMEM = 512 * APITCH * (int)sizeof(__nv_bfloat16) + 64 * (int)sizeof(float);
    cudaFuncSetAttribute(attn_mma, cudaFuncAttributeMaxDynamicSharedMemorySize, ASMEM);
    attn_mma<<<dim3(BB * HEADS, LSEQ / 128), 256, ASMEM>>>(tao);

    // FC projection
    split_bf16<<<NW / 1024, 256>>>(W[3], NW, 1);            // -> g_Whi/g_Wlo
    gemm_mma<<<gg, 256>>>(Bv[3], out, 3);
}

// round 13
// speedup vs baseline: 2.7150x; 1.1177x over previous
#include <cuda_runtime.h>
#include <cuda_bf16.h>
#include <cstdint>

#define LSEQ 2048
#define BB 2
#define HIDD 1024
#define HEADS 16
#define DH 64
#define NTOK (LSEQ*BB)
#define NACT (NTOK*HIDD)     /* 4194304 = 1<<22 */
#define NW   (HIDD*HIDD)     /* 1048576 = 1<<20 */

// ---------------- scratch (device globals; no allocation allowed) ----------------
__device__ float g_mb[BB*LSEQ];
// activation splits for q,k,v inputs (concatenated, offset p*NACT)
__device__ __align__(16) __nv_bfloat16 g_Ahi[(size_t)3*NACT];
__device__ __align__(16) __nv_bfloat16 g_Alo[(size_t)3*NACT];
// weight splits for wq,wk,wv,wfc (concatenated, offset p*NW)
__device__ __align__(16) __nv_bfloat16 g_WhiA[(size_t)4*NW];
__device__ __align__(16) __nv_bfloat16 g_WloA[(size_t)4*NW];
// ctx (attention output) splits = FC input
__device__ __align__(16) __nv_bfloat16 g_Chi[(size_t)NACT];
__device__ __align__(16) __nv_bfloat16 g_Clo[(size_t)NACT];
// Q/K: [b*16+h][l][d], V: [b*16+h][d][l] (pre-transposed for PV mma)
__device__ __align__(16) __nv_bfloat16 g_Qhi[(size_t)BB*HEADS*LSEQ*DH];
__device__ __align__(16) __nv_bfloat16 g_Qlo[(size_t)BB*HEADS*LSEQ*DH];
__device__ __align__(16) __nv_bfloat16 g_Khi[(size_t)BB*HEADS*LSEQ*DH];
__device__ __align__(16) __nv_bfloat16 g_Klo[(size_t)BB*HEADS*LSEQ*DH];
__device__ __align__(16) __nv_bfloat16 g_Vhi[(size_t)BB*HEADS*LSEQ*DH];
__device__ __align__(16) __nv_bfloat16 g_Vlo[(size_t)BB*HEADS*LSEQ*DH];

// ---------------- helpers ----------------
__device__ __forceinline__ void split1(float v, __nv_bfloat16& hi, __nv_bfloat16& lo) {
    hi = __float2bfloat16(v);
    lo = __float2bfloat16(v - __bfloat162float(hi));
}
__device__ __forceinline__ void split2u(float a, float b, uint32_t& hi, uint32_t& lo) {
    __nv_bfloat16 ha, la, hb, lb;
    split1(a, ha, la); split1(b, hb, lb);
    __nv_bfloat162 H(ha, hb), L(la, lb);
    hi = *reinterpret_cast<uint32_t*>(&H);
    lo = *reinterpret_cast<uint32_t*>(&L);
}
__device__ __forceinline__ void mma16816(float* c, const uint32_t* a, const uint32_t* b) {
    asm volatile(
        "mma.sync.aligned.m16n8k16.row.col.f32.bf16.bf16.f32 "
        "{%0,%1,%2,%3}, {%4,%5,%6,%7}, {%8,%9}, {%0,%1,%2,%3};\n"
        : "+f"(c[0]), "+f"(c[1]), "+f"(c[2]), "+f"(c[3])
        : "r"(a[0]), "r"(a[1]), "r"(a[2]), "r"(a[3]), "r"(b[0]), "r"(b[1]));
}
__device__ __forceinline__ uint32_t s2u(const void* p) {
    return (uint32_t)__cvta_generic_to_shared(p);
}
__device__ __forceinline__ void cpa16(uint32_t s, const void* g) {
    asm volatile("cp.async.cg.shared.global [%0], [%1], 16;" :: "r"(s), "l"(g));
}
__device__ __forceinline__ void cpa4(uint32_t s, const void* g) {
    asm volatile("cp.async.ca.shared.global [%0], [%1], 4;" :: "r"(s), "l"(g));
}
#define CP_COMMIT() asm volatile("cp.async.commit_group;")
#define CP_WAIT0()  asm volatile("cp.async.wait_group 0;")

// ---------------- mask normalization (dtype-robust) ----------------
__global__ void prep_mask(const unsigned char* __restrict__ mraw) {
    __shared__ int s_u8, s_f32;
    int t = threadIdx.x;
    if (t == 0) { s_u8 = 0; s_f32 = 0; }
    __syncthreads();
    int u8 = 0, f32 = 0;
    for (int i = t; i < BB*LSEQ; i += blockDim.x) {
        unsigned char v = mraw[i];
        if (v > 1) f32 = 1;
        if ((i & 3) != 0 && v) u8 = 1;
    }
    if (u8)  atomicOr(&s_u8, 1);
    if (f32) atomicOr(&s_f32, 1);
    __syncthreads();
    int is_f32 = s_f32, is_u8 = s_u8;
    for (int i = t; i < BB*LSEQ; i += blockDim.x) {
        bool m;
        if (is_f32)      m = (((const float*)mraw)[i] != 0.0f);
        else if (is_u8)  m = (mraw[i] != 0);
        else             m = (((const int*)mraw)[i] != 0);
        g_mb[i] = m ? -1e30f : 0.0f;
    }
}

// ---------------- batched splits ----------------
__global__ __launch_bounds__(256) void split_acts(
    const float* __restrict__ a0, const float* __restrict__ a1, const float* __restrict__ a2)
{
    int i = (blockIdx.x * blockDim.x + threadIdx.x) * 4;   // < 3*NACT
    int p = i >> 22;
    const float* src = (p == 0) ? a0 : (p == 1) ? a1 : a2;
    float4 v = *(const float4*)(src + (i & (NACT - 1)));
    uint32_t h0, l0, h1, l1;
    split2u(v.x, v.y, h0, l0);
    split2u(v.z, v.w, h1, l1);
    *(uint32_t*)(g_Ahi + i)     = h0;  *(uint32_t*)(g_Ahi + i + 2) = h1;
    *(uint32_t*)(g_Alo + i)     = l0;  *(uint32_t*)(g_Alo + i + 2) = l1;
}

__global__ __launch_bounds__(256) void split_weights(
    const float* __restrict__ w0, const float* __restrict__ w1,
    const float* __restrict__ w2, const float* __restrict__ w3)
{
    int i = (blockIdx.x * blockDim.x + threadIdx.x) * 4;   // < 4*NW
    int p = i >> 20;
    const float* src = (p == 0) ? w0 : (p == 1) ? w1 : (p == 2) ? w2 : w3;
    float4 v = *(const float4*)(src + (i & (NW - 1)));
    uint32_t h0, l0, h1, l1;
    split2u(v.x, v.y, h0, l0);
    split2u(v.z, v.w, h1, l1);
    *(uint32_t*)(g_WhiA + i)     = h0;  *(uint32_t*)(g_WhiA + i + 2) = h1;
    *(uint32_t*)(g_WloA + i)     = l0;  *(uint32_t*)(g_WloA + i + 2) = l1;
}

// ---------------- tensor-core GEMM: Y = X @ W^T + bias (3xBF16 split) ----------------
// cp.async 2-stage pipeline. p = blockIdx.z (QKV launch) or 3 (FC launch).
// p 0: Q (pre-scaled 0.125 -> g_Qhi/lo [bh][l][d])
// p 1: K (-> g_Khi/lo [bh][l][d])
// p 2: V (-> g_Vhi/lo [bh][d][l] TRANSPOSED)
// p 3: f32 [r][o] into Yext (FC -> d_out), X from g_Chi/g_Clo
#define GPITCH 40
#define GSTG (128*GPITCH)   /* 5120 elems per array per stage */

__global__ __launch_bounds__(256) void gemm_mma(
    const float* __restrict__ b0, const float* __restrict__ b1,
    const float* __restrict__ b2, float* __restrict__ Yext, int fc)
{
    extern __shared__ __nv_bfloat16 smg[];   // 2 stages * 4 arrays * GSTG
    int p = fc ? 3 : blockIdx.z;
    const float* bias = fc ? b0 : (p == 0 ? b0 : (p == 1 ? b1 : b2));
    const __nv_bfloat16* Xhi = fc ? g_Chi : g_Ahi + (size_t)p * NACT;
    const __nv_bfloat16* Xlo = fc ? g_Clo : g_Alo + (size_t)p * NACT;
    const __nv_bfloat16* Whi = g_WhiA + (size_t)p * NW;
    const __nv_bfloat16* Wlo = g_WloA + (size_t)p * NW;

    int tid = threadIdx.x;
    int m0 = blockIdx.y * 128, n0 = blockIdx.x * 128;
    int lane = tid & 31, wid = tid >> 5;
    int wm = wid >> 2, wn = wid & 3;
    int g = lane >> 2, t = lane & 3;
    int lrow = tid >> 1, lcol = (tid & 1) * 16;

    const size_t arow = (size_t)(m0 + lrow) * HIDD + lcol;
    const size_t wrow = (size_t)(n0 + lrow) * HIDD + lcol;

    auto issue = [&](int it, int s) {
        __nv_bfloat16* dA = smg + s * 4 * GSTG + lrow * GPITCH + lcol;
        int k0 = it * 32;
        cpa16(s2u(dA),            Xhi + arow + k0);  cpa16(s2u(dA + 8),            Xhi + arow + k0 + 8);
        cpa16(s2u(dA + GSTG),     Xlo + arow + k0);  cpa16(s2u(dA + GSTG + 8),     Xlo + arow + k0 + 8);
        cpa16(s2u(dA + 2*GSTG),   Whi + wrow + k0);  cpa16(s2u(dA + 2*GSTG + 8),   Whi + wrow + k0 + 8);
        cpa16(s2u(dA + 3*GSTG),   Wlo + wrow + k0);  cpa16(s2u(dA + 3*GSTG + 8),   Wlo + wrow + k0 + 8);
    };

    float c[4][4][4];
#pragma unroll
    for (int i = 0; i < 4; i++)
#pragma unroll
        for (int j = 0; j < 4; j++)
#pragma unroll
            for (int r = 0; r < 4; r++) c[i][j][r] = 0.0f;

    issue(0, 0); CP_COMMIT();

    for (int it = 0; it < HIDD / 32; it++) {
        CP_WAIT0();
        __syncthreads();
        if (it + 1 < HIDD / 32) { issue(it + 1, (it + 1) & 1); CP_COMMIT(); }

        const __nv_bfloat16* st   = smg + (it & 1) * 4 * GSTG;
        const __nv_bfloat16* sAhi = st;
        const __nv_bfloat16* sAlo = st + GSTG;
        const __nv_bfloat16* sBhi = st + 2 * GSTG;
        const __nv_bfloat16* sBlo = st + 3 * GSTG;

#pragma unroll
        for (int ks = 0; ks < 2; ks++) {
            int kk = ks * 16 + t * 2;
            uint32_t ah[4][4], al[4][4], bh[4][2], bl[4][2];
#pragma unroll
            for (int mf = 0; mf < 4; mf++) {
                int r0 = (wm * 64 + mf * 16 + g) * GPITCH + kk;
                ah[mf][0] = *(const uint32_t*)&sAhi[r0];
                ah[mf][1] = *(const uint32_t*)&sAhi[r0 + 8 * GPITCH];
                ah[mf][2] = *(const uint32_t*)&sAhi[r0 + 8];
                ah[mf][3] = *(const uint32_t*)&sAhi[r0 + 8 * GPITCH + 8];
                al[mf][0] = *(const uint32_t*)&sAlo[r0];
                al[mf][1] = *(const uint32_t*)&sAlo[r0 + 8 * GPITCH];
                al[mf][2] = *(const uint32_t*)&sAlo[r0 + 8];
                al[mf][3] = *(const uint32_t*)&sAlo[r0 + 8 * GPITCH + 8];
            }
#pragma unroll
            for (int nf = 0; nf < 4; nf++) {
                int r0 = (wn * 32 + nf * 8 + g) * GPITCH + kk;
                bh[nf][0] = *(const uint32_t*)&sBhi[r0];
                bh[nf][1] = *(const uint32_t*)&sBhi[r0 + 8];
                bl[nf][0] = *(const uint32_t*)&sBlo[r0];
                bl[nf][1] = *(const uint32_t*)&sBlo[r0 + 8];
            }
#pragma unroll
            for (int mf = 0; mf < 4; mf++)
#pragma unroll
                for (int nf = 0; nf < 4; nf++) {
                    mma16816(c[mf][nf], ah[mf], bh[nf]);
                    mma16816(c[mf][nf], al[mf], bh[nf]);
                    mma16816(c[mf][nf], ah[mf], bl[nf]);
                }
        }
        __syncthreads();
    }

    float qs = (p == 0) ? 0.125f : 1.0f;   // fold DH^-0.5 into Q (exact pow2)
#pragma unroll
    for (int mf = 0; mf < 4; mf++) {
#pragma unroll
        for (int nf = 0; nf < 4; nf++) {
            int r = m0 + wm * 64 + mf * 16 + g;
            int o = n0 + wn * 32 + nf * 8 + t * 2;
            float bb0 = bias[o], bb1 = bias[o + 1];
            float v00 = c[mf][nf][0] + bb0, v01 = c[mf][nf][1] + bb1;
            float v10 = c[mf][nf][2] + bb0, v11 = c[mf][nf][3] + bb1;
            if (p == 3) {
                *(float2*)&Yext[(size_t)r * HIDD + o]       = make_float2(v00, v01);
                *(float2*)&Yext[(size_t)(r + 8) * HIDD + o] = make_float2(v10, v11);
            } else {
                int h = o >> 6, d = o & 63;
                if (p == 2) {   // V transposed [bh][d][l]
#pragma unroll
                    for (int rr = 0; rr < 2; rr++) {
                        int r2 = r + rr * 8;
                        int l = r2 >> 1, bb = r2 & 1;
                        size_t vb = ((size_t)((bb * HEADS + h) * DH + d)) * LSEQ + l;
                        __nv_bfloat16 hi, lo;
                        float va = rr ? v10 : v00, vbv = rr ? v11 : v01;
                        split1(va, hi, lo);  g_Vhi[vb] = hi;        g_Vlo[vb] = lo;
                        split1(vbv, hi, lo); g_Vhi[vb + LSEQ] = hi; g_Vlo[vb + LSEQ] = lo;
                    }
                } else {        // Q/K [bh][l][d]
                    __nv_bfloat16* dh = (p == 0) ? g_Qhi : g_Khi;
                    __nv_bfloat16* dl = (p == 0) ? g_Qlo : g_Klo;
#pragma unroll
                    for (int rr = 0; rr < 2; rr++) {
                        int r2 = r + rr * 8;
                        int l = r2 >> 1, bb = r2 & 1;
                        size_t qb = ((size_t)((bb * HEADS + h) * LSEQ + l)) * DH + d;
                        uint32_t hi, lo;
                        split2u((rr ? v10 : v00) * qs, (rr ? v11 : v01) * qs, hi, lo);
                        *(uint32_t*)&dh[qb] = hi;
                        *(uint32_t*)&dl[qb] = lo;
                    }
                }
            }
        }
    }
}

// ---------------- flash attention on tensor cores (cp.async pipelined) ----------------
#define APITCH 72
#define AQ  (128*APITCH)   /* 9216 */
#define AKV (64*APITCH)    /* 4608 */

__global__ __launch_bounds__(256) void attn_mma(const float* __restrict__ tao) {
    extern __shared__ __nv_bfloat16 smb[];
    __nv_bfloat16* sQh = smb;                       // [128][APITCH] cols=d
    __nv_bfloat16* sQl = smb + AQ;
    // stage s: K hi/lo [64 key][APITCH], V hi/lo [64 d][APITCH] cols=key
    float* sMb = (float*)(smb + 2 * AQ + 8 * AKV);  // [2][64]

    int bh = blockIdx.x;
    int b = bh >> 4, h = bh & 15;
    int q0 = blockIdx.y * 128;
    int tid = threadIdx.x;
    int lane = tid & 31, wid = tid >> 5;
    int g = lane >> 2, t = lane & 3;

    float tt = tao[h];
    float nh = -0.5f / (tt * tt * tt * tt);

    size_t qk_base = (size_t)bh * LSEQ * DH;   // Q/K: [bh][l][d]
    size_t v_base  = (size_t)bh * DH * LSEQ;   // V:   [bh][d][l]

    auto issue_kv = [&](int tix, int s) {
        int k0 = tix * 64;
        __nv_bfloat16* st = smb + 2 * AQ + s * 4 * AKV;
#pragma unroll
        for (int i0 = 0; i0 < 2; i0++) {
            int i = tid + i0 * 256;
            int row = i >> 3, d0 = (i & 7) * 8;
            size_t go = qk_base + (size_t)(k0 + row) * DH + d0;
            int so = row * APITCH + d0;
            cpa16(s2u(st + so),           g_Khi + go);
            cpa16(s2u(st + AKV + so),     g_Klo + go);
            size_t vo = v_base + (size_t)row * LSEQ + k0 + d0;
            cpa16(s2u(st + 2 * AKV + so), g_Vhi + vo);
            cpa16(s2u(st + 3 * AKV + so), g_Vlo + vo);
        }
        if (tid < 64) cpa4(s2u(sMb + s * 64 + tid), g_mb + b * LSEQ + k0 + tid);
    };

    // load Q tile (128 x 64) hi+lo (plain; ordered by first barrier)
    for (int i = tid; i < 1024; i += 256) {
        int row = i >> 3, d0 = (i & 7) * 8;
        size_t go = qk_base + (size_t)(q0 + row) * DH + d0;
        *(uint4*)&sQh[row * APITCH + d0] = *(const uint4*)(g_Qhi + go);
        *(uint4*)&sQl[row * APITCH + d0] = *(const uint4*)(g_Qlo + go);
    }

    float o[8][4];
#pragma unroll
    for (int i = 0; i < 8; i++)
#pragma unroll
        for (int j = 0; j < 4; j++) o[i][j] = 0.0f;
    float m0 = -3.0e38f, m1 = -3.0e38f, l0 = 0.0f, l1 = 0.0f;

    issue_kv(0, 0); CP_COMMIT();

    for (int tix = 0; tix < LSEQ / 64; tix++) {
        int k0 = tix * 64;
        int cur = tix & 1;
        CP_WAIT0();
        __syncthreads();
        if (tix + 1 < LSEQ / 64) { issue_kv(tix + 1, 1 - cur); CP_COMMIT(); }

        const __nv_bfloat16* st  = smb + 2 * AQ + cur * 4 * AKV;
        const __nv_bfloat16* sKh = st;
        const __nv_bfloat16* sKl = st + AKV;
        const __nv_bfloat16* sVh = st + 2 * AKV;
        const __nv_bfloat16* sVl = st + 3 * AKV;
        const float* mbp = sMb + cur * 64;

        // ---- S = Q@K^T (rows wid*16+g, +8; cols nf*8+2t, +1) ----
        float sc[8][4];
#pragma unroll
        for (int nf = 0; nf < 8; nf++)
#pragma unroll
            for (int j = 0; j < 4; j++) sc[nf][j] = 0.0f;

#pragma unroll
        for (int dc = 0; dc < 4; dc++) {
            int kk = dc * 16 + t * 2;
            int r0 = (wid * 16 + g) * APITCH + kk;
            uint32_t ah[4], al[4];
            ah[0] = *(const uint32_t*)&sQh[r0];
            ah[1] = *(const uint32_t*)&sQh[r0 + 8 * APITCH];
            ah[2] = *(const uint32_t*)&sQh[r0 + 8];
            ah[3] = *(const uint32_t*)&sQh[r0 + 8 * APITCH + 8];
            al[0] = *(const uint32_t*)&sQl[r0];
            al[1] = *(const uint32_t*)&sQl[r0 + 8 * APITCH];
            al[2] = *(const uint32_t*)&sQl[r0 + 8];
            al[3] = *(const uint32_t*)&sQl[r0 + 8 * APITCH + 8];
#pragma unroll
            for (int nf = 0; nf < 8; nf++) {
                int rb = (nf * 8 + g) * APITCH + kk;
                uint32_t bh2[2] = {*(const uint32_t*)&sKh[rb], *(const uint32_t*)&sKh[rb + 8]};
                uint32_t bl2[2] = {*(const uint32_t*)&sKl[rb], *(const uint32_t*)&sKl[rb + 8]};
                mma16816(sc[nf], ah, bh2);
                mma16816(sc[nf], al, bh2);
                mma16816(sc[nf], ah, bl2);
            }
        }

        // ---- gaussian bias + key mask ----
        int qr0 = q0 + wid * 16 + g, qr1 = qr0 + 8;
#pragma unroll
        for (int nf = 0; nf < 8; nf++) {
            int kc = k0 + nf * 8 + t * 2;
            float mb0 = mbp[nf * 8 + t * 2], mb1 = mbp[nf * 8 + t * 2 + 1];
            float d0 = (float)(qr0 - kc), d1 = (float)(qr0 - kc - 1);
            float d2 = (float)(qr1 - kc), d3 = (float)(qr1 - kc - 1);
            sc[nf][0] += d0 * d0 * nh + mb0;
            sc[nf][1] += d1 * d1 * nh + mb1;
            sc[nf][2] += d2 * d2 * nh + mb0;
            sc[nf][3] += d3 * d3 * nh + mb1;
        }

        // ---- online softmax (rows live on 4 lanes t=0..3) ----
        float mt0 = -3.0e38f, mt1 = -3.0e38f;
#pragma unroll
        for (int nf = 0; nf < 8; nf++) {
            mt0 = fmaxf(mt0, fmaxf(sc[nf][0], sc[nf][1]));
            mt1 = fmaxf(mt1, fmaxf(sc[nf][2], sc[nf][3]));
        }
        mt0 = fmaxf(mt0, __shfl_xor_sync(0xffffffffu, mt0, 1));
        mt0 = fmaxf(mt0, __shfl_xor_sync(0xffffffffu, mt0, 2));
        mt1 = fmaxf(mt1, __shfl_xor_sync(0xffffffffu, mt1, 1));
        mt1 = fmaxf(mt1, __shfl_xor_sync(0xffffffffu, mt1, 2));
        float mn0 = fmaxf(m0, mt0), mn1 = fmaxf(m1, mt1);
        float c0 = __expf(m0 - mn0), c1 = __expf(m1 - mn1);
        m0 = mn0; m1 = mn1;
        float rs0 = 0.0f, rs1 = 0.0f;
#pragma unroll
        for (int nf = 0; nf < 8; nf++) {
            sc[nf][0] = __expf(sc[nf][0] - mn0);
            sc[nf][1] = __expf(sc[nf][1] - mn0);
            sc[nf][2] = __expf(sc[nf][2] - mn1);
            sc[nf][3] = __expf(sc[nf][3] - mn1);
            rs0 += sc[nf][0] + sc[nf][1];
            rs1 += sc[nf][2] + sc[nf][3];
        }
        rs0 += __shfl_xor_sync(0xffffffffu, rs0, 1);
        rs0 += __shfl_xor_sync(0xffffffffu, rs0, 2);
        rs1 += __shfl_xor_sync(0xffffffffu, rs1, 1);
        rs1 += __shfl_xor_sync(0xffffffffu, rs1, 2);
        l0 = l0 * c0 + rs0;
        l1 = l1 * c1 + rs1;
#pragma unroll
        for (int dt = 0; dt < 8; dt++) {
            o[dt][0] *= c0; o[dt][1] *= c0;
            o[dt][2] *= c1; o[dt][3] *= c1;
        }

        // ---- O += P@V : P C-frags -> A-frags in registers ----
#pragma unroll
        for (int kc = 0; kc < 4; kc++) {
            uint32_t aph[4], apl[4];
            split2u(sc[2*kc][0],   sc[2*kc][1],   aph[0], apl[0]);
            split2u(sc[2*kc][2],   sc[2*kc][3],   aph[1], apl[1]);
            split2u(sc[2*kc+1][0], sc[2*kc+1][1], aph[2], apl[2]);
            split2u(sc[2*kc+1][2], sc[2*kc+1][3], aph[3], apl[3]);
#pragma unroll
            for (int dt = 0; dt < 8; dt++) {
                int rb = (dt * 8 + g) * APITCH + kc * 16 + t * 2;
                uint32_t bh2[2] = {*(const uint32_t*)&sVh[rb], *(const uint32_t*)&sVh[rb + 8]};
                uint32_t bl2[2] = {*(const uint32_t*)&sVl[rb], *(const uint32_t*)&sVl[rb + 8]};
                mma16816(o[dt], aph, bh2);
                mma16816(o[dt], apl, bh2);
                mma16816(o[dt], aph, bl2);
            }
        }
        __syncthreads();
    }

    // ---- epilogue: write ctx directly as bf16 splits (FC input) ----
    float inv0 = 1.0f / l0, inv1 = 1.0f / l1;
    int qg0 = q0 + wid * 16 + g;
    int r0 = qg0 * BB + b, r1 = (qg0 + 8) * BB + b;
#pragma unroll
    for (int dt = 0; dt < 8; dt++) {
        int oc = h * DH + dt * 8 + t * 2;
        uint32_t hi, lo;
        split2u(o[dt][0] * inv0, o[dt][1] * inv0, hi, lo);
        *(uint32_t*)&g_Chi[(size_t)r0 * HIDD + oc] = hi;
        *(uint32_t*)&g_Clo[(size_t)r0 * HIDD + oc] = lo;
        split2u(o[dt][2] * inv1, o[dt][3] * inv1, hi, lo);
        *(uint32_t*)&g_Chi[(size_t)r1 * HIDD + oc] = hi;
        *(uint32_t*)&g_Clo[(size_t)r1 * HIDD + oc] = lo;
    }
}

// ---------------- launcher ----------------
// Inputs classified by element count (robust to metadata ordering):
//   4194304 -> activations (q, k, v)   1048576 -> weights (wq, wk, wv, wfc)
//   4096 -> mask   1024 -> biases (bq, bk, bv, bfc)   16 -> tao
extern "C" void kernel_launch(void* const* d_in, const int* in_sizes, int n_in,
                              void* d_out, int out_size) {
    const float* act[3] = {nullptr, nullptr, nullptr};
    const float* W[4]   = {nullptr, nullptr, nullptr, nullptr};
    const float* Bv[4]  = {nullptr, nullptr, nullptr, nullptr};
    const float* tao = nullptr;
    const unsigned char* mask = nullptr;
    int na = 0, nw = 0, nb = 0;
    for (int i = 0; i < n_in; i++) {
        long s = in_sizes[i];
        if (s == (long)NACT)             { if (na < 3) act[na++] = (const float*)d_in[i]; }
        else if (s == (long)NW)          { if (nw < 4) W[nw++]   = (const float*)d_in[i]; }
        else if (s == (long)HIDD)        { if (nb < 4) Bv[nb++]  = (const float*)d_in[i]; }
        else if (s == (long)HEADS)       { tao = (const float*)d_in[i]; }
        else if (s == (long)BB * LSEQ)   { mask = (const unsigned char*)d_in[i]; }
    }
    float* out = (float*)d_out;

    const int GSMEM = 2 * 4 * GSTG * (int)sizeof(__nv_bfloat16);             // 81920
    const int ASMEM = (2 * AQ + 8 * AKV) * (int)sizeof(__nv_bfloat16) + 512; // 111104
    cudaFuncSetAttribute(gemm_mma, cudaFuncAttributeMaxDynamicSharedMemorySize, GSMEM);
    cudaFuncSetAttribute(attn_mma, cudaFuncAttributeMaxDynamicSharedMemorySize, ASMEM);

    prep_mask<<<1, 1024>>>(mask);
    split_acts<<<3 * NACT / 1024, 256>>>(act[0], act[1], act[2]);
    split_weights<<<4 * NW / 1024, 256>>>(W[0], W[1], W[2], W[3]);

    // QKV projections in ONE launch (z selects q/k/v)
    gemm_mma<<<dim3(HIDD / 128, NTOK / 128, 3), 256, GSMEM>>>(Bv[0], Bv[1], Bv[2], nullptr, 0);

    // attention (writes g_Chi/g_Clo = split ctx, the FC input)
    attn_mma<<<dim3(BB * HEADS, LSEQ / 128), 256, ASMEM>>>(tao);

    // FC projection
    gemm_mma<<<dim3(HIDD / 128, NTOK / 128, 1), 256, GSMEM>>>(Bv[3], nullptr, nullptr, out, 1);
}

// round 14
// speedup vs baseline: 2.7201x; 1.0019x over previous
#include <cuda_runtime.h>
#include <cuda_bf16.h>
#include <cstdint>

#define LSEQ 2048
#define BB 2
#define HIDD 1024
#define HEADS 16
#define DH 64
#define NTOK (LSEQ*BB)
#define NACT (NTOK*HIDD)     /* 4194304 = 1<<22 */
#define NW   (HIDD*HIDD)     /* 1048576 = 1<<20 */

// ---------------- scratch (device globals; no allocation allowed) ----------------
__device__ float g_mb[BB*LSEQ];
// activation splits for q,k,v inputs (concatenated, offset p*NACT)
__device__ __align__(16) __nv_bfloat16 g_Ahi[(size_t)3*NACT];
__device__ __align__(16) __nv_bfloat16 g_Alo[(size_t)3*NACT];
// weight splits for wq,wk,wv,wfc (concatenated, offset p*NW)
__device__ __align__(16) __nv_bfloat16 g_WhiA[(size_t)4*NW];
__device__ __align__(16) __nv_bfloat16 g_WloA[(size_t)4*NW];
// ctx (attention output) splits = FC input
__device__ __align__(16) __nv_bfloat16 g_Chi[(size_t)NACT];
__device__ __align__(16) __nv_bfloat16 g_Clo[(size_t)NACT];
// Q/K: [b*16+h][l][d], V: [b*16+h][d][l] (pre-transposed for PV mma)
__device__ __align__(16) __nv_bfloat16 g_Qhi[(size_t)BB*HEADS*LSEQ*DH];
__device__ __align__(16) __nv_bfloat16 g_Qlo[(size_t)BB*HEADS*LSEQ*DH];
__device__ __align__(16) __nv_bfloat16 g_Khi[(size_t)BB*HEADS*LSEQ*DH];
__device__ __align__(16) __nv_bfloat16 g_Klo[(size_t)BB*HEADS*LSEQ*DH];
__device__ __align__(16) __nv_bfloat16 g_Vhi[(size_t)BB*HEADS*LSEQ*DH];
__device__ __align__(16) __nv_bfloat16 g_Vlo[(size_t)BB*HEADS*LSEQ*DH];

// ---------------- helpers ----------------
__device__ __forceinline__ void split1(float v, __nv_bfloat16& hi, __nv_bfloat16& lo) {
    hi = __float2bfloat16(v);
    lo = __float2bfloat16(v - __bfloat162float(hi));
}
__device__ __forceinline__ void split2u(float a, float b, uint32_t& hi, uint32_t& lo) {
    __nv_bfloat16 ha, la, hb, lb;
    split1(a, ha, la); split1(b, hb, lb);
    __nv_bfloat162 H(ha, hb), L(la, lb);
    hi = *reinterpret_cast<uint32_t*>(&H);
    lo = *reinterpret_cast<uint32_t*>(&L);
}
__device__ __forceinline__ void mma16816(float* c, const uint32_t* a, const uint32_t* b) {
    asm volatile(
        "mma.sync.aligned.m16n8k16.row.col.f32.bf16.bf16.f32 "
        "{%0,%1,%2,%3}, {%4,%5,%6,%7}, {%8,%9}, {%0,%1,%2,%3};\n"
        : "+f"(c[0]), "+f"(c[1]), "+f"(c[2]), "+f"(c[3])
        : "r"(a[0]), "r"(a[1]), "r"(a[2]), "r"(a[3]), "r"(b[0]), "r"(b[1]));
}
__device__ __forceinline__ uint32_t s2u(const void* p) {
    return (uint32_t)__cvta_generic_to_shared(p);
}
__device__ __forceinline__ void cpa16(uint32_t s, const void* g) {
    asm volatile("cp.async.cg.shared.global [%0], [%1], 16;" :: "r"(s), "l"(g));
}
__device__ __forceinline__ void cpa4(uint32_t s, const void* g) {
    asm volatile("cp.async.ca.shared.global [%0], [%1], 4;" :: "r"(s), "l"(g));
}
#define CP_COMMIT() asm volatile("cp.async.commit_group;")
#define CP_WAIT0()  asm volatile("cp.async.wait_group 0;")

// ---------------- mask normalization (dtype-robust) ----------------
__global__ void prep_mask(const unsigned char* __restrict__ mraw) {
    __shared__ int s_u8, s_f32;
    int t = threadIdx.x;
    if (t == 0) { s_u8 = 0; s_f32 = 0; }
    __syncthreads();
    int u8 = 0, f32 = 0;
    for (int i = t; i < BB*LSEQ; i += blockDim.x) {
        unsigned char v = mraw[i];
        if (v > 1) f32 = 1;
        if ((i & 3) != 0 && v) u8 = 1;
    }
    if (u8)  atomicOr(&s_u8, 1);
    if (f32) atomicOr(&s_f32, 1);
    __syncthreads();
    int is_f32 = s_f32, is_u8 = s_u8;
    for (int i = t; i < BB*LSEQ; i += blockDim.x) {
        bool m;
        if (is_f32)      m = (((const float*)mraw)[i] != 0.0f);
        else if (is_u8)  m = (mraw[i] != 0);
        else             m = (((const int*)mraw)[i] != 0);
        g_mb[i] = m ? -1e30f : 0.0f;
    }
}

// ---------------- batched splits ----------------
__global__ __launch_bounds__(256) void split_acts(
    const float* __restrict__ a0, const float* __restrict__ a1, const float* __restrict__ a2)
{
    int i = (blockIdx.x * blockDim.x + threadIdx.x) * 4;   // < 3*NACT
    int p = i >> 22;
    const float* src = (p == 0) ? a0 : (p == 1) ? a1 : a2;
    float4 v = *(const float4*)(src + (i & (NACT - 1)));
    uint32_t h0, l0, h1, l1;
    split2u(v.x, v.y, h0, l0);
    split2u(v.z, v.w, h1, l1);
    *(uint32_t*)(g_Ahi + i)     = h0;  *(uint32_t*)(g_Ahi + i + 2) = h1;
    *(uint32_t*)(g_Alo + i)     = l0;  *(uint32_t*)(g_Alo + i + 2) = l1;
}

__global__ __launch_bounds__(256) void split_weights(
    const float* __restrict__ w0, const float* __restrict__ w1,
    const float* __restrict__ w2, const float* __restrict__ w3)
{
    int i = (blockIdx.x * blockDim.x + threadIdx.x) * 4;   // < 4*NW
    int p = i >> 20;
    const float* src = (p == 0) ? w0 : (p == 1) ? w1 : (p == 2) ? w2 : w3;
    float4 v = *(const float4*)(src + (i & (NW - 1)));
    uint32_t h0, l0, h1, l1;
    split2u(v.x, v.y, h0, l0);
    split2u(v.z, v.w, h1, l1);
    *(uint32_t*)(g_WhiA + i)     = h0;  *(uint32_t*)(g_WhiA + i + 2) = h1;
    *(uint32_t*)(g_WloA + i)     = l0;  *(uint32_t*)(g_WloA + i + 2) = l1;
}

// ---------------- tensor-core GEMM: Y = X @ W^T + bias (3xBF16 split) ----------------
// cp.async 2-stage pipeline. p = blockIdx.z (QKV launch) or 3 (FC launch).
// p 0: Q (pre-scaled 0.125 -> g_Qhi/lo [bh][l][d])
// p 1: K (-> g_Khi/lo [bh][l][d])
// p 2: V (-> g_Vhi/lo [bh][d][l] TRANSPOSED)
// p 3: f32 [r][o] into Yext (FC -> d_out), X from g_Chi/g_Clo
#define GPITCH 40
#define GSTG (128*GPITCH)   /* 5120 elems per array per stage */

__global__ __launch_bounds__(256) void gemm_mma(
    const float* __restrict__ b0, const float* __restrict__ b1,
    const float* __restrict__ b2, float* __restrict__ Yext, int fc)
{
    extern __shared__ __nv_bfloat16 smg[];   // 2 stages * 4 arrays * GSTG
    int p = fc ? 3 : blockIdx.z;
    const float* bias = fc ? b0 : (p == 0 ? b0 : (p == 1 ? b1 : b2));
    const __nv_bfloat16* Xhi = fc ? g_Chi : g_Ahi + (size_t)p * NACT;
    const __nv_bfloat16* Xlo = fc ? g_Clo : g_Alo + (size_t)p * NACT;
    const __nv_bfloat16* Whi = g_WhiA + (size_t)p * NW;
    const __nv_bfloat16* Wlo = g_WloA + (size_t)p * NW;

    int tid = threadIdx.x;
    int m0 = blockIdx.y * 128, n0 = blockIdx.x * 128;
    int lane = tid & 31, wid = tid >> 5;
    int wm = wid >> 2, wn = wid & 3;
    int g = lane >> 2, t = lane & 3;
    int lrow = tid >> 1, lcol = (tid & 1) * 16;

    const size_t arow = (size_t)(m0 + lrow) * HIDD + lcol;
    const size_t wrow = (size_t)(n0 + lrow) * HIDD + lcol;

    auto issue = [&](int it, int s) {
        __nv_bfloat16* dA = smg + s * 4 * GSTG + lrow * GPITCH + lcol;
        int k0 = it * 32;
        cpa16(s2u(dA),            Xhi + arow + k0);  cpa16(s2u(dA + 8),            Xhi + arow + k0 + 8);
        cpa16(s2u(dA + GSTG),     Xlo + arow + k0);  cpa16(s2u(dA + GSTG + 8),     Xlo + arow + k0 + 8);
        cpa16(s2u(dA + 2*GSTG),   Whi + wrow + k0);  cpa16(s2u(dA + 2*GSTG + 8),   Whi + wrow + k0 + 8);
        cpa16(s2u(dA + 3*GSTG),   Wlo + wrow + k0);  cpa16(s2u(dA + 3*GSTG + 8),   Wlo + wrow + k0 + 8);
    };

    float c[4][4][4];
#pragma unroll
    for (int i = 0; i < 4; i++)
#pragma unroll
        for (int j = 0; j < 4; j++)
#pragma unroll
            for (int r = 0; r < 4; r++) c[i][j][r] = 0.0f;

    issue(0, 0); CP_COMMIT();

    for (int it = 0; it < HIDD / 32; it++) {
        CP_WAIT0();
        __syncthreads();
        if (it + 1 < HIDD / 32) { issue(it + 1, (it + 1) & 1); CP_COMMIT(); }

        const __nv_bfloat16* st   = smg + (it & 1) * 4 * GSTG;
        const __nv_bfloat16* sAhi = st;
        const __nv_bfloat16* sAlo = st + GSTG;
        const __nv_bfloat16* sBhi = st + 2 * GSTG;
        const __nv_bfloat16* sBlo = st + 3 * GSTG;

#pragma unroll
        for (int ks = 0; ks < 2; ks++) {
            int kk = ks * 16 + t * 2;
            uint32_t ah[4][4], al[4][4], bh[4][2], bl[4][2];
#pragma unroll
            for (int mf = 0; mf < 4; mf++) {
                int r0 = (wm * 64 + mf * 16 + g) * GPITCH + kk;
                ah[mf][0] = *(const uint32_t*)&sAhi[r0];
                ah[mf][1] = *(const uint32_t*)&sAhi[r0 + 8 * GPITCH];
                ah[mf][2] = *(const uint32_t*)&sAhi[r0 + 8];
                ah[mf][3] = *(const uint32_t*)&sAhi[r0 + 8 * GPITCH + 8];
                al[mf][0] = *(const uint32_t*)&sAlo[r0];
                al[mf][1] = *(const uint32_t*)&sAlo[r0 + 8 * GPITCH];
                al[mf][2] = *(const uint32_t*)&sAlo[r0 + 8];
                al[mf][3] = *(const uint32_t*)&sAlo[r0 + 8 * GPITCH + 8];
            }
#pragma unroll
            for (int nf = 0; nf < 4; nf++) {
                int r0 = (wn * 32 + nf * 8 + g) * GPITCH + kk;
                bh[nf][0] = *(const uint32_t*)&sBhi[r0];
                bh[nf][1] = *(const uint32_t*)&sBhi[r0 + 8];
                bl[nf][0] = *(const uint32_t*)&sBlo[r0];
                bl[nf][1] = *(const uint32_t*)&sBlo[r0 + 8];
            }
#pragma unroll
            for (int mf = 0; mf < 4; mf++)
#pragma unroll
                for (int nf = 0; nf < 4; nf++) {
                    mma16816(c[mf][nf], ah[mf], bh[nf]);
                    mma16816(c[mf][nf], al[mf], bh[nf]);
                    mma16816(c[mf][nf], ah[mf], bl[nf]);
                }
        }
        __syncthreads();
    }

    float qs = (p == 0) ? 0.125f : 1.0f;   // fold DH^-0.5 into Q (exact pow2)
#pragma unroll
    for (int mf = 0; mf < 4; mf++) {
#pragma unroll
        for (int nf = 0; nf < 4; nf++) {
            int r = m0 + wm * 64 + mf * 16 + g;
            int o = n0 + wn * 32 + nf * 8 + t * 2;
            float bb0 = bias[o], bb1 = bias[o + 1];
            float v00 = c[mf][nf][0] + bb0, v01 = c[mf][nf][1] + bb1;
            float v10 = c[mf][nf][2] + bb0, v11 = c[mf][nf][3] + bb1;
            if (p == 3) {
                *(float2*)&Yext[(size_t)r * HIDD + o]       = make_float2(v00, v01);
                *(float2*)&Yext[(size_t)(r + 8) * HIDD + o] = make_float2(v10, v11);
            } else {
                int h = o >> 6, d = o & 63;
                if (p == 2) {   // V transposed [bh][d][l]
#pragma unroll
                    for (int rr = 0; rr < 2; rr++) {
                        int r2 = r + rr * 8;
                        int l = r2 >> 1, bb = r2 & 1;
                        size_t vb = ((size_t)((bb * HEADS + h) * DH + d)) * LSEQ + l;
                        __nv_bfloat16 hi, lo;
                        float va = rr ? v10 : v00, vbv = rr ? v11 : v01;
                        split1(va, hi, lo);  g_Vhi[vb] = hi;        g_Vlo[vb] = lo;
                        split1(vbv, hi, lo); g_Vhi[vb + LSEQ] = hi; g_Vlo[vb + LSEQ] = lo;
                    }
                } else {        // Q/K [bh][l][d]
                    __nv_bfloat16* dh = (p == 0) ? g_Qhi : g_Khi;
                    __nv_bfloat16* dl = (p == 0) ? g_Qlo : g_Klo;
#pragma unroll
                    for (int rr = 0; rr < 2; rr++) {
                        int r2 = r + rr * 8;
                        int l = r2 >> 1, bb = r2 & 1;
                        size_t qb = ((size_t)((bb * HEADS + h) * LSEQ + l)) * DH + d;
                        uint32_t hi, lo;
                        split2u((rr ? v10 : v00) * qs, (rr ? v11 : v01) * qs, hi, lo);
                        *(uint32_t*)&dh[qb] = hi;
                        *(uint32_t*)&dl[qb] = lo;
                    }
                }
            }
        }
    }
}

// ---------------- flash attention on tensor cores (cp.async pipelined) ----------------
#define APITCH 72
#define AQ  (128*APITCH)   /* 9216 */
#define AKV (64*APITCH)    /* 4608 */

__global__ __launch_bounds__(256) void attn_mma(const float* __restrict__ tao) {
    extern __shared__ __nv_bfloat16 smb[];
    __nv_bfloat16* sQh = smb;                       // [128][APITCH] cols=d
    __nv_bfloat16* sQl = smb + AQ;
    // stage s: K hi/lo [64 key][APITCH], V hi/lo [64 d][APITCH] cols=key
    float* sMb = (float*)(smb + 2 * AQ + 8 * AKV);  // [2][64]

    int bh = blockIdx.x;
    int b = bh >> 4, h = bh & 15;
    int q0 = blockIdx.y * 128;
    int tid = threadIdx.x;
    int lane = tid & 31, wid = tid >> 5;
    int g = lane >> 2, t = lane & 3;

    float tt = tao[h];
    float nh = -0.5f / (tt * tt * tt * tt);

    size_t qk_base = (size_t)bh * LSEQ * DH;   // Q/K: [bh][l][d]
    size_t v_base  = (size_t)bh * DH * LSEQ;   // V:   [bh][d][l]

    auto issue_kv = [&](int tix, int s) {
        int k0 = tix * 64;
        __nv_bfloat16* st = smb + 2 * AQ + s * 4 * AKV;
#pragma unroll
        for (int i0 = 0; i0 < 2; i0++) {
            int i = tid + i0 * 256;
            int row = i >> 3, d0 = (i & 7) * 8;
            size_t go = qk_base + (size_t)(k0 + row) * DH + d0;
            int so = row * APITCH + d0;
            cpa16(s2u(st + so),           g_Khi + go);
            cpa16(s2u(st + AKV + so),     g_Klo + go);
            size_t vo = v_base + (size_t)row * LSEQ + k0 + d0;
            cpa16(s2u(st + 2 * AKV + so), g_Vhi + vo);
            cpa16(s2u(st + 3 * AKV + so), g_Vlo + vo);
        }
        if (tid < 64) cpa4(s2u(sMb + s * 64 + tid), g_mb + b * LSEQ + k0 + tid);
    };

    // load Q tile (128 x 64) hi+lo (plain; ordered by first barrier)
    for (int i = tid; i < 1024; i += 256) {
        int row = i >> 3, d0 = (i & 7) * 8;
        size_t go = qk_base + (size_t)(q0 + row) * DH + d0;
        *(uint4*)&sQh[row * APITCH + d0] = *(const uint4*)(g_Qhi + go);
        *(uint4*)&sQl[row * APITCH + d0] = *(const uint4*)(g_Qlo + go);
    }

    float o[8][4];
#pragma unroll
    for (int i = 0; i < 8; i++)
#pragma unroll
        for (int j = 0; j < 4; j++) o[i][j] = 0.0f;
    float m0 = -3.0e38f, m1 = -3.0e38f, l0 = 0.0f, l1 = 0.0f;

    issue_kv(0, 0); CP_COMMIT();

    for (int tix = 0; tix < LSEQ / 64; tix++) {
        int k0 = tix * 64;
        int cur = tix & 1;
        CP_WAIT0();
        __syncthreads();
        if (tix + 1 < LSEQ / 64) { issue_kv(tix + 1, 1 - cur); CP_COMMIT(); }

        const __nv_bfloat16* st  = smb + 2 * AQ + cur * 4 * AKV;
        const __nv_bfloat16* sKh = st;
        const __nv_bfloat16* sKl = st + AKV;
        const __nv_bfloat16* sVh = st + 2 * AKV;
        const __nv_bfloat16* sVl = st + 3 * AKV;
        const float* mbp = sMb + cur * 64;

        // ---- S = Q@K^T (rows wid*16+g, +8; cols nf*8+2t, +1) ----
        float sc[8][4];
#pragma unroll
        for (int nf = 0; nf < 8; nf++)
#pragma unroll
            for (int j = 0; j < 4; j++) sc[nf][j] = 0.0f;

#pragma unroll
        for (int dc = 0; dc < 4; dc++) {
            int kk = dc * 16 + t * 2;
            int r0 = (wid * 16 + g) * APITCH + kk;
            uint32_t ah[4], al[4];
            ah[0] = *(const uint32_t*)&sQh[r0];
            ah[1] = *(const uint32_t*)&sQh[r0 + 8 * APITCH];
            ah[2] = *(const uint32_t*)&sQh[r0 + 8];
            ah[3] = *(const uint32_t*)&sQh[r0 + 8 * APITCH + 8];
            al[0] = *(const uint32_t*)&sQl[r0];
            al[1] = *(const uint32_t*)&sQl[r0 + 8 * APITCH];
            al[2] = *(const uint32_t*)&sQl[r0 + 8];
            al[3] = *(const uint32_t*)&sQl[r0 + 8 * APITCH + 8];
#pragma unroll
            for (int nf = 0; nf < 8; nf++) {
                int rb = (nf * 8 + g) * APITCH + kk;
                uint32_t bh2[2] = {*(const uint32_t*)&sKh[rb], *(const uint32_t*)&sKh[rb + 8]};
                uint32_t bl2[2] = {*(const uint32_t*)&sKl[rb], *(const uint32_t*)&sKl[rb + 8]};
                mma16816(sc[nf], ah, bh2);
                mma16816(sc[nf], al, bh2);
                mma16816(sc[nf], ah, bl2);
            }
        }

        // ---- gaussian bias + key mask ----
        int qr0 = q0 + wid * 16 + g, qr1 = qr0 + 8;
#pragma unroll
        for (int nf = 0; nf < 8; nf++) {
            int kc = k0 + nf * 8 + t * 2;
            float mb0 = mbp[nf * 8 + t * 2], mb1 = mbp[nf * 8 + t * 2 + 1];
            float d0 = (float)(qr0 - kc), d1 = (float)(qr0 - kc - 1);
            float d2 = (float)(qr1 - kc), d3 = (float)(qr1 - kc - 1);
            sc[nf][0] += d0 * d0 * nh + mb0;
            sc[nf][1] += d1 * d1 * nh + mb1;
            sc[nf][2] += d2 * d2 * nh + mb0;
            sc[nf][3] += d3 * d3 * nh + mb1;
        }

        // ---- online softmax (rows live on 4 lanes t=0..3) ----
        float mt0 = -3.0e38f, mt1 = -3.0e38f;
#pragma unroll
        for (int nf = 0; nf < 8; nf++) {
            mt0 = fmaxf(mt0, fmaxf(sc[nf][0], sc[nf][1]));
            mt1 = fmaxf(mt1, fmaxf(sc[nf][2], sc[nf][3]));
        }
        mt0 = fmaxf(mt0, __shfl_xor_sync(0xffffffffu, mt0, 1));
        mt0 = fmaxf(mt0, __shfl_xor_sync(0xffffffffu, mt0, 2));
        mt1 = fmaxf(mt1, __shfl_xor_sync(0xffffffffu, mt1, 1));
        mt1 = fmaxf(mt1, __shfl_xor_sync(0xffffffffu, mt1, 2));
        float mn0 = fmaxf(m0, mt0), mn1 = fmaxf(m1, mt1);
        float c0 = __expf(m0 - mn0), c1 = __expf(m1 - mn1);
        m0 = mn0; m1 = mn1;
        float rs0 = 0.0f, rs1 = 0.0f;
#pragma unroll
        for (int nf = 0; nf < 8; nf++) {
            sc[nf][0] = __expf(sc[nf][0] - mn0);
            sc[nf][1] = __expf(sc[nf][1] - mn0);
            sc[nf][2] = __expf(sc[nf][2] - mn1);
            sc[nf][3] = __expf(sc[nf][3] - mn1);
            rs0 += sc[nf][0] + sc[nf][1];
            rs1 += sc[nf][2] + sc[nf][3];
        }
        rs0 += __shfl_xor_sync(0xffffffffu, rs0, 1);
        rs0 += __shfl_xor_sync(0xffffffffu, rs0, 2);
        rs1 += __shfl_xor_sync(0xffffffffu, rs1, 1);
        rs1 += __shfl_xor_sync(0xffffffffu, rs1, 2);
        l0 = l0 * c0 + rs0;
        l1 = l1 * c1 + rs1;
#pragma unroll
        for (int dt = 0; dt < 8; dt++) {
            o[dt][0] *= c0; o[dt][1] *= c0;
            o[dt][2] *= c1; o[dt][3] *= c1;
        }

        // ---- O += P@V : P C-frags -> A-frags in registers ----
#pragma unroll
        for (int kc = 0; kc < 4; kc++) {
            uint32_t aph[4], apl[4];
            split2u(sc[2*kc][0],   sc[2*kc][1],   aph[0], apl[0]);
            split2u(sc[2*kc][2],   sc[2*kc][3],   aph[1], apl[1]);
            split2u(sc[2*kc+1][0], sc[2*kc+1][1], aph[2], apl[2]);
            split2u(sc[2*kc+1][2], sc[2*kc+1][3], aph[3], apl[3]);
#pragma unroll
            for (int dt = 0; dt < 8; dt++) {
                int rb = (dt * 8 + g) * APITCH + kc * 16 + t * 2;
                uint32_t bh2[2] = {*(const uint32_t*)&sVh[rb], *(const uint32_t*)&sVh[rb + 8]};
                uint32_t bl2[2] = {*(const uint32_t*)&sVl[rb], *(const uint32_t*)&sVl[rb + 8]};
                mma16816(o[dt], aph, bh2);
                mma16816(o[dt], apl, bh2);
                mma16816(o[dt], aph, bl2);
            }
        }
        __syncthreads();
    }

    // ---- epilogue: write ctx directly as bf16 splits (FC input) ----
    float inv0 = 1.0f / l0, inv1 = 1.0f / l1;
    int qg0 = q0 + wid * 16 + g;
    int r0 = qg0 * BB + b, r1 = (qg0 + 8) * BB + b;
#pragma unroll
    for (int dt = 0; dt < 8; dt++) {
        int oc = h * DH + dt * 8 + t * 2;
        uint32_t hi, lo;
        split2u(o[dt][0] * inv0, o[dt][1] * inv0, hi, lo);
        *(uint32_t*)&g_Chi[(size_t)r0 * HIDD + oc] = hi;
        *(uint32_t*)&g_Clo[(size_t)r0 * HIDD + oc] = lo;
        split2u(o[dt][2] * inv1, o[dt][3] * inv1, hi, lo);
        *(uint32_t*)&g_Chi[(size_t)r1 * HIDD + oc] = hi;
        *(uint32_t*)&g_Clo[(size_t)r1 * HIDD + oc] = lo;
    }
}

// ---------------- launcher ----------------
// Inputs classified by element count (robust to metadata ordering):
//   4194304 -> activations (q, k, v)   1048576 -> weights (wq, wk, wv, wfc)
//   4096 -> mask   1024 -> biases (bq, bk, bv, bfc)   16 -> tao
extern "C" void kernel_launch(void* const* d_in, const int* in_sizes, int n_in,
                              void* d_out, int out_size) {
    const float* act[3] = {nullptr, nullptr, nullptr};
    const float* W[4]   = {nullptr, nullptr, nullptr, nullptr};
    const float* Bv[4]  = {nullptr, nullptr, nullptr, nullptr};
    const float* tao = nullptr;
    const unsigned char* mask = nullptr;
    int na = 0, nw = 0, nb = 0;
    for (int i = 0; i < n_in; i++) {
        long s = in_sizes[i];
        if (s == (long)NACT)             { if (na < 3) act[na++] = (const float*)d_in[i]; }
        else if (s == (long)NW)          { if (nw < 4) W[nw++]   = (const float*)d_in[i]; }
        else if (s == (long)HIDD)        { if (nb < 4) Bv[nb++]  = (const float*)d_in[i]; }
        else if (s == (long)HEADS)       { tao = (const float*)d_in[i]; }
        else if (s == (long)BB * LSEQ)   { mask = (const unsigned char*)d_in[i]; }
    }
    float* out = (float*)d_out;

    const int GSMEM = 2 * 4 * GSTG * (int)sizeof(__nv_bfloat16);             // 81920
    const int ASMEM = (2 * AQ + 8 * AKV) * (int)sizeof(__nv_bfloat16) + 512; // 111104
    cudaFuncSetAttribute(gemm_mma, cudaFuncAttributeMaxDynamicSharedMemorySize, GSMEM);
    cudaFuncSetAttribute(attn_mma, cudaFuncAttributeMaxDynamicSharedMemorySize, ASMEM);

    prep_mask<<<1, 1024>>>(mask);
    split_acts<<<3 * NACT / 1024, 256>>>(act[0], act[1], act[2]);
    split_weights<<<4 * NW / 1024, 256>>>(W[0], W[1], W[2], W[3]);

    // QKV projections in ONE launch (z selects q/k/v)
    gemm_mma<<<dim3(HIDD / 128, NTOK / 128, 3), 256, GSMEM>>>(Bv[0], Bv[1], Bv[2], nullptr, 0);

    // attention (writes g_Chi/g_Clo = split ctx, the FC input)
    attn_mma<<<dim3(BB * HEADS, LSEQ / 128), 256, ASMEM>>>(tao);

    // FC projection
    gemm_mma<<<dim3(HIDD / 128, NTOK / 128, 1), 256, GSMEM>>>(Bv[3], nullptr, nullptr, out, 1);
}

// round 15
// speedup vs baseline: 3.0348x; 1.1157x over previous
#include <cuda_runtime.h>
#include <cuda_bf16.h>
#include <cstdint>

#define LSEQ 2048
#define BB 2
#define HIDD 1024
#define HEADS 16
#define DH 64
#define NTOK (LSEQ*BB)
#define NACT (NTOK*HIDD)     /* 4194304 = 1<<22 */
#define NW   (HIDD*HIDD)     /* 1048576 = 1<<20 */

// ---------------- scratch (device globals; no allocation allowed) ----------------
__device__ float g_mb[BB*LSEQ];
__device__ __align__(16) __nv_bfloat16 g_Ahi[(size_t)3*NACT];
__device__ __align__(16) __nv_bfloat16 g_Alo[(size_t)3*NACT];
__device__ __align__(16) __nv_bfloat16 g_WhiA[(size_t)4*NW];
__device__ __align__(16) __nv_bfloat16 g_WloA[(size_t)4*NW];
__device__ __align__(16) __nv_bfloat16 g_Chi[(size_t)NACT];
__device__ __align__(16) __nv_bfloat16 g_Clo[(size_t)NACT];
// Q/K: [b*16+h][l][d], V: [b*16+h][d][l] (pre-transposed for PV mma)
__device__ __align__(16) __nv_bfloat16 g_Qhi[(size_t)BB*HEADS*LSEQ*DH];
__device__ __align__(16) __nv_bfloat16 g_Qlo[(size_t)BB*HEADS*LSEQ*DH];
__device__ __align__(16) __nv_bfloat16 g_Khi[(size_t)BB*HEADS*LSEQ*DH];
__device__ __align__(16) __nv_bfloat16 g_Klo[(size_t)BB*HEADS*LSEQ*DH];
__device__ __align__(16) __nv_bfloat16 g_Vhi[(size_t)BB*HEADS*LSEQ*DH];
__device__ __align__(16) __nv_bfloat16 g_Vlo[(size_t)BB*HEADS*LSEQ*DH];

// ---------------- helpers ----------------
__device__ __forceinline__ void split1(float v, __nv_bfloat16& hi, __nv_bfloat16& lo) {
    hi = __float2bfloat16(v);
    lo = __float2bfloat16(v - __bfloat162float(hi));
}
__device__ __forceinline__ void split2u(float a, float b, uint32_t& hi, uint32_t& lo) {
    __nv_bfloat16 ha, la, hb, lb;
    split1(a, ha, la); split1(b, hb, lb);
    __nv_bfloat162 H(ha, hb), L(la, lb);
    hi = *reinterpret_cast<uint32_t*>(&H);
    lo = *reinterpret_cast<uint32_t*>(&L);
}
__device__ __forceinline__ void mma16816(float* c, const uint32_t* a, const uint32_t* b) {
    asm volatile(
        "mma.sync.aligned.m16n8k16.row.col.f32.bf16.bf16.f32 "
        "{%0,%1,%2,%3}, {%4,%5,%6,%7}, {%8,%9}, {%0,%1,%2,%3};\n"
        : "+f"(c[0]), "+f"(c[1]), "+f"(c[2]), "+f"(c[3])
        : "r"(a[0]), "r"(a[1]), "r"(a[2]), "r"(a[3]), "r"(b[0]), "r"(b[1]));
}
__device__ __forceinline__ void ldsmx4(uint32_t* r, uint32_t a) {
    asm volatile("ldmatrix.sync.aligned.m8n8.x4.shared.b16 {%0,%1,%2,%3}, [%4];"
                 : "=r"(r[0]), "=r"(r[1]), "=r"(r[2]), "=r"(r[3]) : "r"(a));
}
__device__ __forceinline__ uint32_t s2u(const void* p) {
    return (uint32_t)__cvta_generic_to_shared(p);
}
__device__ __forceinline__ void cpa16(uint32_t s, const void* g) {
    asm volatile("cp.async.cg.shared.global [%0], [%1], 16;" :: "r"(s), "l"(g));
}
__device__ __forceinline__ void cpa4(uint32_t s, const void* g) {
    asm volatile("cp.async.ca.shared.global [%0], [%1], 4;" :: "r"(s), "l"(g));
}
#define CP_COMMIT() asm volatile("cp.async.commit_group;")
#define CP_WAIT0()  asm volatile("cp.async.wait_group 0;")

// ---------------- mask normalization (dtype-robust) ----------------
__global__ void prep_mask(const unsigned char* __restrict__ mraw) {
    __shared__ int s_u8, s_f32;
    int t = threadIdx.x;
    if (t == 0) { s_u8 = 0; s_f32 = 0; }
    __syncthreads();
    int u8 = 0, f32 = 0;
    for (int i = t; i < BB*LSEQ; i += blockDim.x) {
        unsigned char v = mraw[i];
        if (v > 1) f32 = 1;
        if ((i & 3) != 0 && v) u8 = 1;
    }
    if (u8)  atomicOr(&s_u8, 1);
    if (f32) atomicOr(&s_f32, 1);
    __syncthreads();
    int is_f32 = s_f32, is_u8 = s_u8;
    for (int i = t; i < BB*LSEQ; i += blockDim.x) {
        bool m;
        if (is_f32)      m = (((const float*)mraw)[i] != 0.0f);
        else if (is_u8)  m = (mraw[i] != 0);
        else             m = (((const int*)mraw)[i] != 0);
        g_mb[i] = m ? -1e30f : 0.0f;
    }
}

// ---------------- batched splits ----------------
__global__ __launch_bounds__(256) void split_acts(
    const float* __restrict__ a0, const float* __restrict__ a1, const float* __restrict__ a2)
{
    int i = (blockIdx.x * blockDim.x + threadIdx.x) * 4;
    int p = i >> 22;
    const float* src = (p == 0) ? a0 : (p == 1) ? a1 : a2;
    float4 v = *(const float4*)(src + (i & (NACT - 1)));
    uint32_t h0, l0, h1, l1;
    split2u(v.x, v.y, h0, l0);
    split2u(v.z, v.w, h1, l1);
    *(uint32_t*)(g_Ahi + i)     = h0;  *(uint32_t*)(g_Ahi + i + 2) = h1;
    *(uint32_t*)(g_Alo + i)     = l0;  *(uint32_t*)(g_Alo + i + 2) = l1;
}

__global__ __launch_bounds__(256) void split_weights(
    const float* __restrict__ w0, const float* __restrict__ w1,
    const float* __restrict__ w2, const float* __restrict__ w3)
{
    int i = (blockIdx.x * blockDim.x + threadIdx.x) * 4;
    int p = i >> 20;
    const float* src = (p == 0) ? w0 : (p == 1) ? w1 : (p == 2) ? w2 : w3;
    float4 v = *(const float4*)(src + (i & (NW - 1)));
    uint32_t h0, l0, h1, l1;
    split2u(v.x, v.y, h0, l0);
    split2u(v.z, v.w, h1, l1);
    *(uint32_t*)(g_WhiA + i)     = h0;  *(uint32_t*)(g_WhiA + i + 2) = h1;
    *(uint32_t*)(g_WloA + i)     = l0;  *(uint32_t*)(g_WloA + i + 2) = l1;
}

// ---------------- tensor-core GEMM: Y = X @ W^T + bias (3xBF16 split) ----------------
#define GPITCH 40
#define GSTG (128*GPITCH)   /* elems per array per stage */

__global__ __launch_bounds__(256, 2) void gemm_mma(
    const float* __restrict__ b0, const float* __restrict__ b1,
    const float* __restrict__ b2, float* __restrict__ Yext, int fc)
{
    extern __shared__ __nv_bfloat16 smg[];   // 2 stages * 4 arrays * GSTG
    int p = fc ? 3 : blockIdx.z;
    const float* bias = fc ? b0 : (p == 0 ? b0 : (p == 1 ? b1 : b2));
    const __nv_bfloat16* Xhi = fc ? g_Chi : g_Ahi + (size_t)p * NACT;
    const __nv_bfloat16* Xlo = fc ? g_Clo : g_Alo + (size_t)p * NACT;
    const __nv_bfloat16* Whi = g_WhiA + (size_t)p * NW;
    const __nv_bfloat16* Wlo = g_WloA + (size_t)p * NW;

    int tid = threadIdx.x;
    int m0 = blockIdx.y * 128, n0 = blockIdx.x * 128;
    int lane = tid & 31, wid = tid >> 5;
    int wm = wid >> 2, wn = wid & 3;
    int g = lane >> 2, t = lane & 3;
    int lrow = tid >> 1, lcol = (tid & 1) * 16;

    // ldmatrix lane offsets (A: m16k16 as 4x m8n8; B: n16k16 as 4x m8n8)
    int a_r = ((lane >> 3) & 1) * 8 + (lane & 7);
    int a_c = ((lane >> 4) & 1) * 8;
    int b_r = ((lane >> 4) & 1) * 8 + (lane & 7);
    int b_c = ((lane >> 3) & 1) * 8;

    const uint32_t usm = s2u(smg);
    const uint32_t GB = GPITCH * 2;      // row stride bytes
    const uint32_t ABB = GSTG * 2;       // array stride bytes
    const uint32_t aoff = usm + (uint32_t)(wm * 64 + a_r) * GB + a_c * 2;
    const uint32_t boff = usm + (uint32_t)(wn * 32 + b_r) * GB + b_c * 2 + 2 * ABB;

    const size_t arow = (size_t)(m0 + lrow) * HIDD + lcol;
    const size_t wrow = (size_t)(n0 + lrow) * HIDD + lcol;

    auto issue = [&](int it, int s) {
        __nv_bfloat16* dA = smg + s * 4 * GSTG + lrow * GPITCH + lcol;
        int k0 = it * 32;
        cpa16(s2u(dA),            Xhi + arow + k0);  cpa16(s2u(dA + 8),            Xhi + arow + k0 + 8);
        cpa16(s2u(dA + GSTG),     Xlo + arow + k0);  cpa16(s2u(dA + GSTG + 8),     Xlo + arow + k0 + 8);
        cpa16(s2u(dA + 2*GSTG),   Whi + wrow + k0);  cpa16(s2u(dA + 2*GSTG + 8),   Whi + wrow + k0 + 8);
        cpa16(s2u(dA + 3*GSTG),   Wlo + wrow + k0);  cpa16(s2u(dA + 3*GSTG + 8),   Wlo + wrow + k0 + 8);
    };

    float c[4][4][4];
#pragma unroll
    for (int i = 0; i < 4; i++)
#pragma unroll
        for (int j = 0; j < 4; j++)
#pragma unroll
            for (int r = 0; r < 4; r++) c[i][j][r] = 0.0f;

    issue(0, 0); CP_COMMIT();

    for (int it = 0; it < HIDD / 32; it++) {
        CP_WAIT0();
        __syncthreads();   // single barrier: separates compute(it-1) from issue(it+1)
        if (it + 1 < HIDD / 32) { issue(it + 1, (it + 1) & 1); CP_COMMIT(); }

        uint32_t stb = (uint32_t)(it & 1) * (4 * ABB);
#pragma unroll
        for (int ks = 0; ks < 2; ks++) {
            uint32_t ko = ks * 32;   // 16 elems * 2 B
            uint32_t ah[4][4], al[4][4], bh[2][4], bl[2][4];
#pragma unroll
            for (int mf = 0; mf < 4; mf++) {
                uint32_t a0 = aoff + stb + (uint32_t)mf * (16 * GB) + ko;
                ldsmx4(ah[mf], a0);
                ldsmx4(al[mf], a0 + ABB);
            }
#pragma unroll
            for (int pq = 0; pq < 2; pq++) {
                uint32_t bq = boff + stb + (uint32_t)pq * (16 * GB) + ko;
                ldsmx4(bh[pq], bq);
                ldsmx4(bl[pq], bq + ABB);
            }
#pragma unroll
            for (int mf = 0; mf < 4; mf++)
#pragma unroll
                for (int nf = 0; nf < 4; nf++) {
                    const uint32_t* bhp = &bh[nf >> 1][(nf & 1) * 2];
                    const uint32_t* blp = &bl[nf >> 1][(nf & 1) * 2];
                    mma16816(c[mf][nf], ah[mf], bhp);
                    mma16816(c[mf][nf], al[mf], bhp);
                    mma16816(c[mf][nf], ah[mf], blp);
                }
        }
    }

    float qs = (p == 0) ? 0.125f : 1.0f;   // fold DH^-0.5 into Q (exact pow2)
#pragma unroll
    for (int mf = 0; mf < 4; mf++) {
#pragma unroll
        for (int nf = 0; nf < 4; nf++) {
            int r = m0 + wm * 64 + mf * 16 + g;
            int o = n0 + wn * 32 + nf * 8 + t * 2;
            float bb0 = bias[o], bb1 = bias[o + 1];
            float v00 = c[mf][nf][0] + bb0, v01 = c[mf][nf][1] + bb1;
            float v10 = c[mf][nf][2] + bb0, v11 = c[mf][nf][3] + bb1;
            if (p == 3) {
                *(float2*)&Yext[(size_t)r * HIDD + o]       = make_float2(v00, v01);
                *(float2*)&Yext[(size_t)(r + 8) * HIDD + o] = make_float2(v10, v11);
            } else {
                int h = o >> 6, d = o & 63;
                if (p == 2) {   // V transposed [bh][d][l]
#pragma unroll
                    for (int rr = 0; rr < 2; rr++) {
                        int r2 = r + rr * 8;
                        int l = r2 >> 1, bb = r2 & 1;
                        size_t vb = ((size_t)((bb * HEADS + h) * DH + d)) * LSEQ + l;
                        __nv_bfloat16 hi, lo;
                        float va = rr ? v10 : v00, vbv = rr ? v11 : v01;
                        split1(va, hi, lo);  g_Vhi[vb] = hi;        g_Vlo[vb] = lo;
                        split1(vbv, hi, lo); g_Vhi[vb + LSEQ] = hi; g_Vlo[vb + LSEQ] = lo;
                    }
                } else {        // Q/K [bh][l][d]
                    __nv_bfloat16* dh = (p == 0) ? g_Qhi : g_Khi;
                    __nv_bfloat16* dl = (p == 0) ? g_Qlo : g_Klo;
#pragma unroll
                    for (int rr = 0; rr < 2; rr++) {
                        int r2 = r + rr * 8;
                        int l = r2 >> 1, bb = r2 & 1;
                        size_t qb = ((size_t)((bb * HEADS + h) * LSEQ + l)) * DH + d;
                        uint32_t hi, lo;
                        split2u((rr ? v10 : v00) * qs, (rr ? v11 : v01) * qs, hi, lo);
                        *(uint32_t*)&dh[qb] = hi;
                        *(uint32_t*)&dl[qb] = lo;
                    }
                }
            }
        }
    }
}

// ---------------- flash attention on tensor cores (cp.async + ldmatrix) ----------------
#define APITCH 72
#define AQ  (128*APITCH)
#define AKV (64*APITCH)

__global__ __launch_bounds__(256, 2) void attn_mma(const float* __restrict__ tao) {
    extern __shared__ __nv_bfloat16 smb[];
    __nv_bfloat16* sQh = smb;                       // [128][APITCH] cols=d
    __nv_bfloat16* sQl = smb + AQ;
    float* sMb = (float*)(smb + 2 * AQ + 8 * AKV);  // [2][64]

    int bh = blockIdx.x;
    int b = bh >> 4, h = bh & 15;
    int q0 = blockIdx.y * 128;
    int tid = threadIdx.x;
    int lane = tid & 31, wid = tid >> 5;
    int g = lane >> 2, t = lane & 3;

    int a_r = ((lane >> 3) & 1) * 8 + (lane & 7);
    int a_c = ((lane >> 4) & 1) * 8;
    int b_r = ((lane >> 4) & 1) * 8 + (lane & 7);
    int b_c = ((lane >> 3) & 1) * 8;

    float tt = tao[h];
    float nh = -0.5f / (tt * tt * tt * tt);

    size_t qk_base = (size_t)bh * LSEQ * DH;   // Q/K: [bh][l][d]
    size_t v_base  = (size_t)bh * DH * LSEQ;   // V:   [bh][d][l]

    const uint32_t usm = s2u(smb);
    const uint32_t APB  = APITCH * 2;   // row stride bytes
    const uint32_t AQB  = AQ * 2;
    const uint32_t AKVB = AKV * 2;
    const uint32_t qoff  = usm + (uint32_t)(wid * 16 + a_r) * APB + a_c * 2;          // sQh
    const uint32_t kvoff = usm + 2 * AQB + (uint32_t)b_r * APB + b_c * 2;             // stage base + row

    auto issue_kv = [&](int tix, int s) {
        int k0 = tix * 64;
        __nv_bfloat16* st = smb + 2 * AQ + s * 4 * AKV;
#pragma unroll
        for (int i0 = 0; i0 < 2; i0++) {
            int i = tid + i0 * 256;
            int row = i >> 3, d0 = (i & 7) * 8;
            size_t go = qk_base + (size_t)(k0 + row) * DH + d0;
            int so = row * APITCH + d0;
            cpa16(s2u(st + so),           g_Khi + go);
            cpa16(s2u(st + AKV + so),     g_Klo + go);
            size_t vo = v_base + (size_t)row * LSEQ + k0 + d0;
            cpa16(s2u(st + 2 * AKV + so), g_Vhi + vo);
            cpa16(s2u(st + 3 * AKV + so), g_Vlo + vo);
        }
        if (tid < 64) cpa4(s2u(sMb + s * 64 + tid), g_mb + b * LSEQ + k0 + tid);
    };

    // load Q tile (128 x 64) hi+lo
    for (int i = tid; i < 1024; i += 256) {
        int row = i >> 3, d0 = (i & 7) * 8;
        size_t go = qk_base + (size_t)(q0 + row) * DH + d0;
        *(uint4*)&sQh[row * APITCH + d0] = *(const uint4*)(g_Qhi + go);
        *(uint4*)&sQl[row * APITCH + d0] = *(const uint4*)(g_Qlo + go);
    }

    float o[8][4];
#pragma unroll
    for (int i = 0; i < 8; i++)
#pragma unroll
        for (int j = 0; j < 4; j++) o[i][j] = 0.0f;
    float m0 = -3.0e38f, m1 = -3.0e38f, l0 = 0.0f, l1 = 0.0f;

    issue_kv(0, 0); CP_COMMIT();

    for (int tix = 0; tix < LSEQ / 64; tix++) {
        int k0 = tix * 64;
        int cur = tix & 1;
        CP_WAIT0();
        __syncthreads();   // single barrier per tile
        if (tix + 1 < LSEQ / 64) { issue_kv(tix + 1, 1 - cur); CP_COMMIT(); }

        uint32_t stb = (uint32_t)cur * (4 * AKVB);
        const float* mbp = sMb + cur * 64;

        // ---- S = Q@K^T ----
        float sc[8][4];
#pragma unroll
        for (int nf = 0; nf < 8; nf++)
#pragma unroll
            for (int j = 0; j < 4; j++) sc[nf][j] = 0.0f;

#pragma unroll
        for (int dc = 0; dc < 4; dc++) {
            uint32_t ko = dc * 32;
            uint32_t ah[4], al[4];
            ldsmx4(ah, qoff + ko);
            ldsmx4(al, qoff + AQB + ko);
#pragma unroll
            for (int pq = 0; pq < 4; pq++) {
                uint32_t kq = kvoff + stb + (uint32_t)pq * (16 * APB) + ko;
                uint32_t kh[4], kl[4];
                ldsmx4(kh, kq);
                ldsmx4(kl, kq + AKVB);
#pragma unroll
                for (int hf = 0; hf < 2; hf++) {
                    float* s = sc[2 * pq + hf];
                    mma16816(s, ah, &kh[hf * 2]);
                    mma16816(s, al, &kh[hf * 2]);
                    mma16816(s, ah, &kl[hf * 2]);
                }
            }
        }

        // ---- gaussian bias + key mask ----
        int qr0 = q0 + wid * 16 + g, qr1 = qr0 + 8;
#pragma unroll
        for (int nf = 0; nf < 8; nf++) {
            int kc = k0 + nf * 8 + t * 2;
            float mb0 = mbp[nf * 8 + t * 2], mb1 = mbp[nf * 8 + t * 2 + 1];
            float d0 = (float)(qr0 - kc), d1 = (float)(qr0 - kc - 1);
            float d2 = (float)(qr1 - kc), d3 = (float)(qr1 - kc - 1);
            sc[nf][0] += d0 * d0 * nh + mb0;
            sc[nf][1] += d1 * d1 * nh + mb1;
            sc[nf][2] += d2 * d2 * nh + mb0;
            sc[nf][3] += d3 * d3 * nh + mb1;
        }

        // ---- online softmax (rows live on 4 lanes t=0..3) ----
        float mt0 = -3.0e38f, mt1 = -3.0e38f;
#pragma unroll
        for (int nf = 0; nf < 8; nf++) {
            mt0 = fmaxf(mt0, fmaxf(sc[nf][0], sc[nf][1]));
            mt1 = fmaxf(mt1, fmaxf(sc[nf][2], sc[nf][3]));
        }
        mt0 = fmaxf(mt0, __shfl_xor_sync(0xffffffffu, mt0, 1));
        mt0 = fmaxf(mt0, __shfl_xor_sync(0xffffffffu, mt0, 2));
        mt1 = fmaxf(mt1, __shfl_xor_sync(0xffffffffu, mt1, 1));
        mt1 = fmaxf(mt1, __shfl_xor_sync(0xffffffffu, mt1, 2));
        float mn0 = fmaxf(m0, mt0), mn1 = fmaxf(m1, mt1);
        float c0 = __expf(m0 - mn0), c1 = __expf(m1 - mn1);
        m0 = mn0; m1 = mn1;
        float rs0 = 0.0f, rs1 = 0.0f;
#pragma unroll
        for (int nf = 0; nf < 8; nf++) {
            sc[nf][0] = __expf(sc[nf][0] - mn0);
            sc[nf][1] = __expf(sc[nf][1] - mn0);
            sc[nf][2] = __expf(sc[nf][2] - mn1);
            sc[nf][3] = __expf(sc[nf][3] - mn1);
            rs0 += sc[nf][0] + sc[nf][1];
            rs1 += sc[nf][2] + sc[nf][3];
        }
        rs0 += __shfl_xor_sync(0xffffffffu, rs0, 1);
        rs0 += __shfl_xor_sync(0xffffffffu, rs0, 2);
        rs1 += __shfl_xor_sync(0xffffffffu, rs1, 1);
        rs1 += __shfl_xor_sync(0xffffffffu, rs1, 2);
        l0 = l0 * c0 + rs0;
        l1 = l1 * c1 + rs1;
#pragma unroll
        for (int dt = 0; dt < 8; dt++) {
            o[dt][0] *= c0; o[dt][1] *= c0;
            o[dt][2] *= c1; o[dt][3] *= c1;
        }

        // ---- O += P@V : P C-frags -> A-frags in registers ----
#pragma unroll
        for (int kc = 0; kc < 4; kc++) {
            uint32_t aph[4], apl[4];
            split2u(sc[2*kc][0],   sc[2*kc][1],   aph[0], apl[0]);
            split2u(sc[2*kc][2],   sc[2*kc][3],   aph[1], apl[1]);
            split2u(sc[2*kc+1][0], sc[2*kc+1][1], aph[2], apl[2]);
            split2u(sc[2*kc+1][2], sc[2*kc+1][3], aph[3], apl[3]);
            uint32_t ko = kc * 32;
#pragma unroll
            for (int pq = 0; pq < 4; pq++) {
                uint32_t vq = kvoff + stb + 2 * AKVB + (uint32_t)pq * (16 * APB) + ko;
                uint32_t vh[4], vl[4];
                ldsmx4(vh, vq);
                ldsmx4(vl, vq + AKVB);
#pragma unroll
                for (int hf = 0; hf < 2; hf++) {
                    float* op = o[2 * pq + hf];
                    mma16816(op, aph, &vh[hf * 2]);
                    mma16816(op, apl, &vh[hf * 2]);
                    mma16816(op, aph, &vl[hf * 2]);
                }
            }
        }
    }

    // ---- epilogue: write ctx directly as bf16 splits (FC input) ----
    float inv0 = 1.0f / l0, inv1 = 1.0f / l1;
    int qg0 = q0 + wid * 16 + g;
    int r0 = qg0 * BB + b, r1 = (qg0 + 8) * BB + b;
#pragma unroll
    for (int dt = 0; dt < 8; dt++) {
        int oc = h * DH + dt * 8 + t * 2;
        uint32_t hi, lo;
        split2u(o[dt][0] * inv0, o[dt][1] * inv0, hi, lo);
        *(uint32_t*)&g_Chi[(size_t)r0 * HIDD + oc] = hi;
        *(uint32_t*)&g_Clo[(size_t)r0 * HIDD + oc] = lo;
        split2u(o[dt][2] * inv1, o[dt][3] * inv1, hi, lo);
        *(uint32_t*)&g_Chi[(size_t)r1 * HIDD + oc] = hi;
        *(uint32_t*)&g_Clo[(size_t)r1 * HIDD + oc] = lo;
    }
}

// ---------------- launcher ----------------
// Inputs classified by element count (robust to metadata ordering):
//   4194304 -> activations (q, k, v)   1048576 -> weights (wq, wk, wv, wfc)
//   4096 -> mask   1024 -> biases (bq, bk, bv, bfc)   16 -> tao
extern "C" void kernel_launch(void* const* d_in, const int* in_sizes, int n_in,
                              void* d_out, int out_size) {
    const float* act[3] = {nullptr, nullptr, nullptr};
    const float* W[4]   = {nullptr, nullptr, nullptr, nullptr};
    const float* Bv[4]  = {nullptr, nullptr, nullptr, nullptr};
    const float* tao = nullptr;
    const unsigned char* mask = nullptr;
    int na = 0, nw = 0, nb = 0;
    for (int i = 0; i < n_in; i++) {
        long s = in_sizes[i];
        if (s == (long)NACT)             { if (na < 3) act[na++] = (const float*)d_in[i]; }
        else if (s == (long)NW)          { if (nw < 4) W[nw++]   = (const float*)d_in[i]; }
        else if (s == (long)HIDD)        { if (nb < 4) Bv[nb++]  = (const float*)d_in[i]; }
        else if (s == (long)HEADS)       { tao = (const float*)d_in[i]; }
        else if (s == (long)BB * LSEQ)   { mask = (const unsigned char*)d_in[i]; }
    }
    float* out = (float*)d_out;

    const int GSMEM = 2 * 4 * GSTG * (int)sizeof(__nv_bfloat16);             // 81920
    const int ASMEM = (2 * AQ + 8 * AKV) * (int)sizeof(__nv_bfloat16) + 512; // 111104
    cudaFuncSetAttribute(gemm_mma, cudaFuncAttributeMaxDynamicSharedMemorySize, GSMEM);
    cudaFuncSetAttribute(attn_mma, cudaFuncAttributeMaxDynamicSharedMemorySize, ASMEM);

    prep_mask<<<1, 1024>>>(mask);
    split_acts<<<3 * NACT / 1024, 256>>>(act[0], act[1], act[2]);
    split_weights<<<4 * NW / 1024, 256>>>(W[0], W[1], W[2], W[3]);

    // QKV projections in ONE launch (z selects q/k/v)
    gemm_mma<<<dim3(HIDD / 128, NTOK / 128, 3), 256, GSMEM>>>(Bv[0], Bv[1], Bv[2], nullptr, 0);

    // attention (writes g_Chi/g_Clo = split ctx, the FC input)
    attn_mma<<<dim3(BB * HEADS, LSEQ / 128), 256, ASMEM>>>(tao);

    // FC projection
    gemm_mma<<<dim3(HIDD / 128, NTOK / 128, 1), 256, GSMEM>>>(Bv[3], nullptr, nullptr, out, 1);
}

// round 16
// speedup vs baseline: 3.0359x; 1.0004x over previous
#include <cuda_runtime.h>
#include <cuda_bf16.h>
#include <cstdint>

#define LSEQ 2048
#define BB 2
#define HIDD 1024
#define HEADS 16
#define DH 64
#define NTOK (LSEQ*BB)
#define NACT (NTOK*HIDD)     /* 4194304 = 1<<22 */
#define NW   (HIDD*HIDD)     /* 1048576 = 1<<20 */

// ---------------- scratch (device globals; no allocation allowed) ----------------
__device__ float g_mb[BB*LSEQ];
__device__ __align__(16) __nv_bfloat16 g_Ahi[(size_t)3*NACT];
__device__ __align__(16) __nv_bfloat16 g_Alo[(size_t)3*NACT];
__device__ __align__(16) __nv_bfloat16 g_WhiA[(size_t)4*NW];
__device__ __align__(16) __nv_bfloat16 g_WloA[(size_t)4*NW];
__device__ __align__(16) __nv_bfloat16 g_Chi[(size_t)NACT];
__device__ __align__(16) __nv_bfloat16 g_Clo[(size_t)NACT];
// Q/K: [b*16+h][l][d], V: [b*16+h][d][l] (pre-transposed for PV mma)
__device__ __align__(16) __nv_bfloat16 g_Qhi[(size_t)BB*HEADS*LSEQ*DH];
__device__ __align__(16) __nv_bfloat16 g_Qlo[(size_t)BB*HEADS*LSEQ*DH];
__device__ __align__(16) __nv_bfloat16 g_Khi[(size_t)BB*HEADS*LSEQ*DH];
__device__ __align__(16) __nv_bfloat16 g_Klo[(size_t)BB*HEADS*LSEQ*DH];
__device__ __align__(16) __nv_bfloat16 g_Vhi[(size_t)BB*HEADS*LSEQ*DH];
__device__ __align__(16) __nv_bfloat16 g_Vlo[(size_t)BB*HEADS*LSEQ*DH];

// ---------------- helpers ----------------
__device__ __forceinline__ void split1(float v, __nv_bfloat16& hi, __nv_bfloat16& lo) {
    hi = __float2bfloat16(v);
    lo = __float2bfloat16(v - __bfloat162float(hi));
}
__device__ __forceinline__ void split2u(float a, float b, uint32_t& hi, uint32_t& lo) {
    __nv_bfloat16 ha, la, hb, lb;
    split1(a, ha, la); split1(b, hb, lb);
    __nv_bfloat162 H(ha, hb), L(la, lb);
    hi = *reinterpret_cast<uint32_t*>(&H);
    lo = *reinterpret_cast<uint32_t*>(&L);
}
__device__ __forceinline__ void mma16816(float* c, const uint32_t* a, const uint32_t* b) {
    asm volatile(
        "mma.sync.aligned.m16n8k16.row.col.f32.bf16.bf16.f32 "
        "{%0,%1,%2,%3}, {%4,%5,%6,%7}, {%8,%9}, {%0,%1,%2,%3};\n"
        : "+f"(c[0]), "+f"(c[1]), "+f"(c[2]), "+f"(c[3])
        : "r"(a[0]), "r"(a[1]), "r"(a[2]), "r"(a[3]), "r"(b[0]), "r"(b[1]));
}
__device__ __forceinline__ void ldsmx4(uint32_t* r, uint32_t a) {
    asm volatile("ldmatrix.sync.aligned.m8n8.x4.shared.b16 {%0,%1,%2,%3}, [%4];"
                 : "=r"(r[0]), "=r"(r[1]), "=r"(r[2]), "=r"(r[3]) : "r"(a));
}
__device__ __forceinline__ uint32_t s2u(const void* p) {
    return (uint32_t)__cvta_generic_to_shared(p);
}
__device__ __forceinline__ void cpa16(uint32_t s, const void* g) {
    asm volatile("cp.async.cg.shared.global [%0], [%1], 16;" :: "r"(s), "l"(g));
}
__device__ __forceinline__ void cpa4(uint32_t s, const void* g) {
    asm volatile("cp.async.ca.shared.global [%0], [%1], 4;" :: "r"(s), "l"(g));
}
#define CP_COMMIT() asm volatile("cp.async.commit_group;")
#define CP_WAIT0()  asm volatile("cp.async.wait_group 0;")

// ---------------- mask normalization (dtype-robust) ----------------
__global__ void prep_mask(const unsigned char* __restrict__ mraw) {
    __shared__ int s_u8, s_f32;
    int t = threadIdx.x;
    if (t == 0) { s_u8 = 0; s_f32 = 0; }
    __syncthreads();
    int u8 = 0, f32 = 0;
    for (int i = t; i < BB*LSEQ; i += blockDim.x) {
        unsigned char v = mraw[i];
        if (v > 1) f32 = 1;
        if ((i & 3) != 0 && v) u8 = 1;
    }
    if (u8)  atomicOr(&s_u8, 1);
    if (f32) atomicOr(&s_f32, 1);
    __syncthreads();
    int is_f32 = s_f32, is_u8 = s_u8;
    for (int i = t; i < BB*LSEQ; i += blockDim.x) {
        bool m;
        if (is_f32)      m = (((const float*)mraw)[i] != 0.0f);
        else if (is_u8)  m = (mraw[i] != 0);
        else             m = (((const int*)mraw)[i] != 0);
        g_mb[i] = m ? -1e30f : 0.0f;
    }
}

// ---------------- batched splits ----------------
__global__ __launch_bounds__(256) void split_acts(
    const float* __restrict__ a0, const float* __restrict__ a1, const float* __restrict__ a2)
{
    int i = (blockIdx.x * blockDim.x + threadIdx.x) * 4;
    int p = i >> 22;
    const float* src = (p == 0) ? a0 : (p == 1) ? a1 : a2;
    float4 v = *(const float4*)(src + (i & (NACT - 1)));
    uint32_t h0, l0, h1, l1;
    split2u(v.x, v.y, h0, l0);
    split2u(v.z, v.w, h1, l1);
    *(uint32_t*)(g_Ahi + i)     = h0;  *(uint32_t*)(g_Ahi + i + 2) = h1;
    *(uint32_t*)(g_Alo + i)     = l0;  *(uint32_t*)(g_Alo + i + 2) = l1;
}

__global__ __launch_bounds__(256) void split_weights(
    const float* __restrict__ w0, const float* __restrict__ w1,
    const float* __restrict__ w2, const float* __restrict__ w3)
{
    int i = (blockIdx.x * blockDim.x + threadIdx.x) * 4;
    int p = i >> 20;
    const float* src = (p == 0) ? w0 : (p == 1) ? w1 : (p == 2) ? w2 : w3;
    float4 v = *(const float4*)(src + (i & (NW - 1)));
    uint32_t h0, l0, h1, l1;
    split2u(v.x, v.y, h0, l0);
    split2u(v.z, v.w, h1, l1);
    *(uint32_t*)(g_WhiA + i)     = h0;  *(uint32_t*)(g_WhiA + i + 2) = h1;
    *(uint32_t*)(g_WloA + i)     = l0;  *(uint32_t*)(g_WloA + i + 2) = l1;
}

// ---------------- tensor-core GEMM: Y = X @ W^T + bias (3xBF16 split) ----------------
#define GPITCH 40
#define GSTG (128*GPITCH)   /* elems per array per stage */

__global__ __launch_bounds__(256, 2) void gemm_mma(
    const float* __restrict__ b0, const float* __restrict__ b1,
    const float* __restrict__ b2, float* __restrict__ Yext, int fc)
{
    extern __shared__ __nv_bfloat16 smg[];   // 2 stages * 4 arrays * GSTG
    int p = fc ? 3 : blockIdx.z;
    const float* bias = fc ? b0 : (p == 0 ? b0 : (p == 1 ? b1 : b2));
    const __nv_bfloat16* Xhi = fc ? g_Chi : g_Ahi + (size_t)p * NACT;
    const __nv_bfloat16* Xlo = fc ? g_Clo : g_Alo + (size_t)p * NACT;
    const __nv_bfloat16* Whi = g_WhiA + (size_t)p * NW;
    const __nv_bfloat16* Wlo = g_WloA + (size_t)p * NW;

    int tid = threadIdx.x;
    int m0 = blockIdx.y * 128, n0 = blockIdx.x * 128;
    int lane = tid & 31, wid = tid >> 5;
    int wm = wid >> 2, wn = wid & 3;
    int g = lane >> 2, t = lane & 3;
    int lrow = tid >> 1, lcol = (tid & 1) * 16;

    // ldmatrix lane offsets (A: m16k16 as 4x m8n8; B: n16k16 as 4x m8n8)
    int a_r = ((lane >> 3) & 1) * 8 + (lane & 7);
    int a_c = ((lane >> 4) & 1) * 8;
    int b_r = ((lane >> 4) & 1) * 8 + (lane & 7);
    int b_c = ((lane >> 3) & 1) * 8;

    const uint32_t usm = s2u(smg);
    const uint32_t GB = GPITCH * 2;      // row stride bytes
    const uint32_t ABB = GSTG * 2;       // array stride bytes
    const uint32_t aoff = usm + (uint32_t)(wm * 64 + a_r) * GB + a_c * 2;
    const uint32_t boff = usm + (uint32_t)(wn * 32 + b_r) * GB + b_c * 2 + 2 * ABB;

    const size_t arow = (size_t)(m0 + lrow) * HIDD + lcol;
    const size_t wrow = (size_t)(n0 + lrow) * HIDD + lcol;

    auto issue = [&](int it, int s) {
        __nv_bfloat16* dA = smg + s * 4 * GSTG + lrow * GPITCH + lcol;
        int k0 = it * 32;
        cpa16(s2u(dA),            Xhi + arow + k0);  cpa16(s2u(dA + 8),            Xhi + arow + k0 + 8);
        cpa16(s2u(dA + GSTG),     Xlo + arow + k0);  cpa16(s2u(dA + GSTG + 8),     Xlo + arow + k0 + 8);
        cpa16(s2u(dA + 2*GSTG),   Whi + wrow + k0);  cpa16(s2u(dA + 2*GSTG + 8),   Whi + wrow + k0 + 8);
        cpa16(s2u(dA + 3*GSTG),   Wlo + wrow + k0);  cpa16(s2u(dA + 3*GSTG + 8),   Wlo + wrow + k0 + 8);
    };

    float c[4][4][4];
#pragma unroll
    for (int i = 0; i < 4; i++)
#pragma unroll
        for (int j = 0; j < 4; j++)
#pragma unroll
            for (int r = 0; r < 4; r++) c[i][j][r] = 0.0f;

    issue(0, 0); CP_COMMIT();

    for (int it = 0; it < HIDD / 32; it++) {
        CP_WAIT0();
        __syncthreads();   // single barrier: separates compute(it-1) from issue(it+1)
        if (it + 1 < HIDD / 32) { issue(it + 1, (it + 1) & 1); CP_COMMIT(); }

        uint32_t stb = (uint32_t)(it & 1) * (4 * ABB);
#pragma unroll
        for (int ks = 0; ks < 2; ks++) {
            uint32_t ko = ks * 32;   // 16 elems * 2 B
            uint32_t ah[4][4], al[4][4], bh[2][4], bl[2][4];
#pragma unroll
            for (int mf = 0; mf < 4; mf++) {
                uint32_t a0 = aoff + stb + (uint32_t)mf * (16 * GB) + ko;
                ldsmx4(ah[mf], a0);
                ldsmx4(al[mf], a0 + ABB);
            }
#pragma unroll
            for (int pq = 0; pq < 2; pq++) {
                uint32_t bq = boff + stb + (uint32_t)pq * (16 * GB) + ko;
                ldsmx4(bh[pq], bq);
                ldsmx4(bl[pq], bq + ABB);
            }
#pragma unroll
            for (int mf = 0; mf < 4; mf++)
#pragma unroll
                for (int nf = 0; nf < 4; nf++) {
                    const uint32_t* bhp = &bh[nf >> 1][(nf & 1) * 2];
                    const uint32_t* blp = &bl[nf >> 1][(nf & 1) * 2];
                    mma16816(c[mf][nf], ah[mf], bhp);
                    mma16816(c[mf][nf], al[mf], bhp);
                    mma16816(c[mf][nf], ah[mf], blp);
                }
        }
    }

    float qs = (p == 0) ? 0.125f : 1.0f;   // fold DH^-0.5 into Q (exact pow2)
#pragma unroll
    for (int mf = 0; mf < 4; mf++) {
#pragma unroll
        for (int nf = 0; nf < 4; nf++) {
            int r = m0 + wm * 64 + mf * 16 + g;
            int o = n0 + wn * 32 + nf * 8 + t * 2;
            float bb0 = bias[o], bb1 = bias[o + 1];
            float v00 = c[mf][nf][0] + bb0, v01 = c[mf][nf][1] + bb1;
            float v10 = c[mf][nf][2] + bb0, v11 = c[mf][nf][3] + bb1;
            if (p == 3) {
                *(float2*)&Yext[(size_t)r * HIDD + o]       = make_float2(v00, v01);
                *(float2*)&Yext[(size_t)(r + 8) * HIDD + o] = make_float2(v10, v11);
            } else {
                int h = o >> 6, d = o & 63;
                if (p == 2) {   // V transposed [bh][d][l]
#pragma unroll
                    for (int rr = 0; rr < 2; rr++) {
                        int r2 = r + rr * 8;
                        int l = r2 >> 1, bb = r2 & 1;
                        size_t vb = ((size_t)((bb * HEADS + h) * DH + d)) * LSEQ + l;
                        __nv_bfloat16 hi, lo;
                        float va = rr ? v10 : v00, vbv = rr ? v11 : v01;
                        split1(va, hi, lo);  g_Vhi[vb] = hi;        g_Vlo[vb] = lo;
                        split1(vbv, hi, lo); g_Vhi[vb + LSEQ] = hi; g_Vlo[vb + LSEQ] = lo;
                    }
                } else {        // Q/K [bh][l][d]
                    __nv_bfloat16* dh = (p == 0) ? g_Qhi : g_Khi;
                    __nv_bfloat16* dl = (p == 0) ? g_Qlo : g_Klo;
#pragma unroll
                    for (int rr = 0; rr < 2; rr++) {
                        int r2 = r + rr * 8;
                        int l = r2 >> 1, bb = r2 & 1;
                        size_t qb = ((size_t)((bb * HEADS + h) * LSEQ + l)) * DH + d;
                        uint32_t hi, lo;
                        split2u((rr ? v10 : v00) * qs, (rr ? v11 : v01) * qs, hi, lo);
                        *(uint32_t*)&dh[qb] = hi;
                        *(uint32_t*)&dl[qb] = lo;
                    }
                }
            }
        }
    }
}

// ---------------- flash attention on tensor cores (cp.async + ldmatrix) ----------------
#define APITCH 72
#define AQ  (128*APITCH)
#define AKV (64*APITCH)

__global__ __launch_bounds__(256, 2) void attn_mma(const float* __restrict__ tao) {
    extern __shared__ __nv_bfloat16 smb[];
    __nv_bfloat16* sQh = smb;                       // [128][APITCH] cols=d
    __nv_bfloat16* sQl = smb + AQ;
    float* sMb = (float*)(smb + 2 * AQ + 8 * AKV);  // [2][64]

    int bh = blockIdx.x;
    int b = bh >> 4, h = bh & 15;
    int q0 = blockIdx.y * 128;
    int tid = threadIdx.x;
    int lane = tid & 31, wid = tid >> 5;
    int g = lane >> 2, t = lane & 3;

    int a_r = ((lane >> 3) & 1) * 8 + (lane & 7);
    int a_c = ((lane >> 4) & 1) * 8;
    int b_r = ((lane >> 4) & 1) * 8 + (lane & 7);
    int b_c = ((lane >> 3) & 1) * 8;

    float tt = tao[h];
    float nh = -0.5f / (tt * tt * tt * tt);

    size_t qk_base = (size_t)bh * LSEQ * DH;   // Q/K: [bh][l][d]
    size_t v_base  = (size_t)bh * DH * LSEQ;   // V:   [bh][d][l]

    const uint32_t usm = s2u(smb);
    const uint32_t APB  = APITCH * 2;   // row stride bytes
    const uint32_t AQB  = AQ * 2;
    const uint32_t AKVB = AKV * 2;
    const uint32_t qoff  = usm + (uint32_t)(wid * 16 + a_r) * APB + a_c * 2;          // sQh
    const uint32_t kvoff = usm + 2 * AQB + (uint32_t)b_r * APB + b_c * 2;             // stage base + row

    auto issue_kv = [&](int tix, int s) {
        int k0 = tix * 64;
        __nv_bfloat16* st = smb + 2 * AQ + s * 4 * AKV;
#pragma unroll
        for (int i0 = 0; i0 < 2; i0++) {
            int i = tid + i0 * 256;
            int row = i >> 3, d0 = (i & 7) * 8;
            size_t go = qk_base + (size_t)(k0 + row) * DH + d0;
            int so = row * APITCH + d0;
            cpa16(s2u(st + so),           g_Khi + go);
            cpa16(s2u(st + AKV + so),     g_Klo + go);
            size_t vo = v_base + (size_t)row * LSEQ + k0 + d0;
            cpa16(s2u(st + 2 * AKV + so), g_Vhi + vo);
            cpa16(s2u(st + 3 * AKV + so), g_Vlo + vo);
        }
        if (tid < 64) cpa4(s2u(sMb + s * 64 + tid), g_mb + b * LSEQ + k0 + tid);
    };

    // load Q tile (128 x 64) hi+lo
    for (int i = tid; i < 1024; i += 256) {
        int row = i >> 3, d0 = (i & 7) * 8;
        size_t go = qk_base + (size_t)(q0 + row) * DH + d0;
        *(uint4*)&sQh[row * APITCH + d0] = *(const uint4*)(g_Qhi + go);
        *(uint4*)&sQl[row * APITCH + d0] = *(const uint4*)(g_Qlo + go);
    }

    float o[8][4];
#pragma unroll
    for (int i = 0; i < 8; i++)
#pragma unroll
        for (int j = 0; j < 4; j++) o[i][j] = 0.0f;
    float m0 = -3.0e38f, m1 = -3.0e38f, l0 = 0.0f, l1 = 0.0f;

    issue_kv(0, 0); CP_COMMIT();

    for (int tix = 0; tix < LSEQ / 64; tix++) {
        int k0 = tix * 64;
        int cur = tix & 1;
        CP_WAIT0();
        __syncthreads();   // single barrier per tile
        if (tix + 1 < LSEQ / 64) { issue_kv(tix + 1, 1 - cur); CP_COMMIT(); }

        uint32_t stb = (uint32_t)cur * (4 * AKVB);
        const float* mbp = sMb + cur * 64;

        // ---- S = Q@K^T ----
        float sc[8][4];
#pragma unroll
        for (int nf = 0; nf < 8; nf++)
#pragma unroll
            for (int j = 0; j < 4; j++) sc[nf][j] = 0.0f;

#pragma unroll
        for (int dc = 0; dc < 4; dc++) {
            uint32_t ko = dc * 32;
            uint32_t ah[4], al[4];
            ldsmx4(ah, qoff + ko);
            ldsmx4(al, qoff + AQB + ko);
#pragma unroll
            for (int pq = 0; pq < 4; pq++) {
                uint32_t kq = kvoff + stb + (uint32_t)pq * (16 * APB) + ko;
                uint32_t kh[4], kl[4];
                ldsmx4(kh, kq);
                ldsmx4(kl, kq + AKVB);
#pragma unroll
                for (int hf = 0; hf < 2; hf++) {
                    float* s = sc[2 * pq + hf];
                    mma16816(s, ah, &kh[hf * 2]);
                    mma16816(s, al, &kh[hf * 2]);
                    mma16816(s, ah, &kl[hf * 2]);
                }
            }
        }

        // ---- gaussian bias + key mask ----
        int qr0 = q0 + wid * 16 + g, qr1 = qr0 + 8;
#pragma unroll
        for (int nf = 0; nf < 8; nf++) {
            int kc = k0 + nf * 8 + t * 2;
            float mb0 = mbp[nf * 8 + t * 2], mb1 = mbp[nf * 8 + t * 2 + 1];
            float d0 = (float)(qr0 - kc), d1 = (float)(qr0 - kc - 1);
            float d2 = (float)(qr1 - kc), d3 = (float)(qr1 - kc - 1);
            sc[nf][0] += d0 * d0 * nh + mb0;
            sc[nf][1] += d1 * d1 * nh + mb1;
            sc[nf][2] += d2 * d2 * nh + mb0;
            sc[nf][3] += d3 * d3 * nh + mb1;
        }

        // ---- online softmax (rows live on 4 lanes t=0..3) ----
        float mt0 = -3.0e38f, mt1 = -3.0e38f;
#pragma unroll
        for (int nf = 0; nf < 8; nf++) {
            mt0 = fmaxf(mt0, fmaxf(sc[nf][0], sc[nf][1]));
            mt1 = fmaxf(mt1, fmaxf(sc[nf][2], sc[nf][3]));
        }
        mt0 = fmaxf(mt0, __shfl_xor_sync(0xffffffffu, mt0, 1));
        mt0 = fmaxf(mt0, __shfl_xor_sync(0xffffffffu, mt0, 2));
        mt1 = fmaxf(mt1, __shfl_xor_sync(0xffffffffu, mt1, 1));
        mt1 = fmaxf(mt1, __shfl_xor_sync(0xffffffffu, mt1, 2));
        float mn0 = fmaxf(m0, mt0), mn1 = fmaxf(m1, mt1);
        float c0 = __expf(m0 - mn0), c1 = __expf(m1 - mn1);
        m0 = mn0; m1 = mn1;
        float rs0 = 0.0f, rs1 = 0.0f;
#pragma unroll
        for (int nf = 0; nf < 8; nf++) {
            sc[nf][0] = __expf(sc[nf][0] - mn0);
            sc[nf][1] = __expf(sc[nf][1] - mn0);
            sc[nf][2] = __expf(sc[nf][2] - mn1);
            sc[nf][3] = __expf(sc[nf][3] - mn1);
            rs0 += sc[nf][0] + sc[nf][1];
            rs1 += sc[nf][2] + sc[nf][3];
        }
        rs0 += __shfl_xor_sync(0xffffffffu, rs0, 1);
        rs0 += __shfl_xor_sync(0xffffffffu, rs0, 2);
        rs1 += __shfl_xor_sync(0xffffffffu, rs1, 1);
        rs1 += __shfl_xor_sync(0xffffffffu, rs1, 2);
        l0 = l0 * c0 + rs0;
        l1 = l1 * c1 + rs1;
#pragma unroll
        for (int dt = 0; dt < 8; dt++) {
            o[dt][0] *= c0; o[dt][1] *= c0;
            o[dt][2] *= c1; o[dt][3] *= c1;
        }

        // ---- O += P@V : P C-frags -> A-frags in registers ----
#pragma unroll
        for (int kc = 0; kc < 4; kc++) {
            uint32_t aph[4], apl[4];
            split2u(sc[2*kc][0],   sc[2*kc][1],   aph[0], apl[0]);
            split2u(sc[2*kc][2],   sc[2*kc][3],   aph[1], apl[1]);
            split2u(sc[2*kc+1][0], sc[2*kc+1][1], aph[2], apl[2]);
            split2u(sc[2*kc+1][2], sc[2*kc+1][3], aph[3], apl[3]);
            uint32_t ko = kc * 32;
#pragma unroll
            for (int pq = 0; pq < 4; pq++) {
                uint32_t vq = kvoff + stb + 2 * AKVB + (uint32_t)pq * (16 * APB) + ko;
                uint32_t vh[4], vl[4];
                ldsmx4(vh, vq);
                ldsmx4(vl, vq + AKVB);
#pragma unroll
                for (int hf = 0; hf < 2; hf++) {
                    float* op = o[2 * pq + hf];
                    mma16816(op, aph, &vh[hf * 2]);
                    mma16816(op, apl, &vh[hf * 2]);
                    mma16816(op, aph, &vl[hf * 2]);
                }
            }
        }
    }

    // ---- epilogue: write ctx directly as bf16 splits (FC input) ----
    float inv0 = 1.0f / l0, inv1 = 1.0f / l1;
    int qg0 = q0 + wid * 16 + g;
    int r0 = qg0 * BB + b, r1 = (qg0 + 8) * BB + b;
#pragma unroll
    for (int dt = 0; dt < 8; dt++) {
        int oc = h * DH + dt * 8 + t * 2;
        uint32_t hi, lo;
        split2u(o[dt][0] * inv0, o[dt][1] * inv0, hi, lo);
        *(uint32_t*)&g_Chi[(size_t)r0 * HIDD + oc] = hi;
        *(uint32_t*)&g_Clo[(size_t)r0 * HIDD + oc] = lo;
        split2u(o[dt][2] * inv1, o[dt][3] * inv1, hi, lo);
        *(uint32_t*)&g_Chi[(size_t)r1 * HIDD + oc] = hi;
        *(uint32_t*)&g_Clo[(size_t)r1 * HIDD + oc] = lo;
    }
}

// ---------------- launcher ----------------
// Inputs classified by element count (robust to metadata ordering):
//   4194304 -> activations (q, k, v)   1048576 -> weights (wq, wk, wv, wfc)
//   4096 -> mask   1024 -> biases (bq, bk, bv, bfc)   16 -> tao
extern "C" void kernel_launch(void* const* d_in, const int* in_sizes, int n_in,
                              void* d_out, int out_size) {
    const float* act[3] = {nullptr, nullptr, nullptr};
    const float* W[4]   = {nullptr, nullptr, nullptr, nullptr};
    const float* Bv[4]  = {nullptr, nullptr, nullptr, nullptr};
    const float* tao = nullptr;
    const unsigned char* mask = nullptr;
    int na = 0, nw = 0, nb = 0;
    for (int i = 0; i < n_in; i++) {
        long s = in_sizes[i];
        if (s == (long)NACT)             { if (na < 3) act[na++] = (const float*)d_in[i]; }
        else if (s == (long)NW)          { if (nw < 4) W[nw++]   = (const float*)d_in[i]; }
        else if (s == (long)HIDD)        { if (nb < 4) Bv[nb++]  = (const float*)d_in[i]; }
        else if (s == (long)HEADS)       { tao = (const float*)d_in[i]; }
        else if (s == (long)BB * LSEQ)   { mask = (const unsigned char*)d_in[i]; }
    }
    float* out = (float*)d_out;

    const int GSMEM = 2 * 4 * GSTG * (int)sizeof(__nv_bfloat16);             // 81920
    const int ASMEM = (2 * AQ + 8 * AKV) * (int)sizeof(__nv_bfloat16) + 512; // 111104
    cudaFuncSetAttribute(gemm_mma, cudaFuncAttributeMaxDynamicSharedMemorySize, GSMEM);
    cudaFuncSetAttribute(attn_mma, cudaFuncAttributeMaxDynamicSharedMemorySize, ASMEM);

    prep_mask<<<1, 1024>>>(mask);
    split_acts<<<3 * NACT / 1024, 256>>>(act[0], act[1], act[2]);
    split_weights<<<4 * NW / 1024, 256>>>(W[0], W[1], W[2], W[3]);

    // QKV projections in ONE launch (z selects q/k/v)
    gemm_mma<<<dim3(HIDD / 128, NTOK / 128, 3), 256, GSMEM>>>(Bv[0], Bv[1], Bv[2], nullptr, 0);

    // attention (writes g_Chi/g_Clo = split ctx, the FC input)
    attn_mma<<<dim3(BB * HEADS, LSEQ / 128), 256, ASMEM>>>(tao);

    // FC projection
    gemm_mma<<<dim3(HIDD / 128, NTOK / 128, 1), 256, GSMEM>>>(Bv[3], nullptr, nullptr, out, 1);
}